// round 1
// baseline (speedup 1.0000x reference)
#include <cuda_runtime.h>

// ---------------- scratch (device globals; no allocation allowed) ----------------
__device__ float g_a1[2048 * 400 * 32];     // conv1 out [n][p=y*20+x][c]
__device__ float g_a2[2048 * 81 * 64];      // conv2 out [n][p=y*9+x][c]
__device__ float g_a3[2048 * 3136];         // conv3 out [n][c*49+p]  (k-major for FC)
__device__ float g_h[2048 * 512];           // CNN feature
__device__ float g_wfeat[2048 * 32];        // h @ Ww + bw
__device__ float g_hidden[2048 * 8256];     // [map readout 8192 | pos_feat 64]
__device__ float g_w1cat[8256 * 128];       // [wpo1 | wv1]
__device__ float g_part[6 * 2048 * 128];    // split-K partials
__device__ float g_z[2048 * 128];           // relu(hidden@W1 + b1)

// ---------------- conv1: 84x84x3 -> 20x20x32, k=8 s=4, fused /255 ----------------
__global__ void __launch_bounds__(256) conv1_kernel(const float* __restrict__ img,
                                                    const float* __restrict__ w1,
                                                    const float* __restrict__ b1,
                                                    float* __restrict__ out) {
    extern __shared__ float sm[];
    float* s_img = sm;            // 21168  [y][x][c]
    float* s_w   = sm + 21168;    // 6144   [(c*64+ky*8+kx)*32 + oc]
    const int n = blockIdx.x, tid = threadIdx.x;
    const float* ip = img + (size_t)n * 21168;
    for (int i = tid; i < 21168; i += 256) s_img[i] = ip[i] * (1.0f / 255.0f);
    for (int i = tid; i < 6144; i += 256) {
        int oc = i / 192, r = i - oc * 192;
        s_w[r * 32 + oc] = w1[i];
    }
    __syncthreads();
    const int ocb = (tid & 3) * 8;
    const int pq = tid >> 2;
    for (int it = 0; it < 2; ++it) {
        int pbase = it * 256 + pq * 4;
        if (pbase >= 400) break;
        int oy = pbase / 20, ox0 = pbase - oy * 20;
        int iy0 = oy * 4, ix0 = ox0 * 4;
        float acc[4][8];
#pragma unroll
        for (int i = 0; i < 4; ++i)
#pragma unroll
            for (int j = 0; j < 8; ++j) acc[i][j] = 0.f;
        for (int ky = 0; ky < 8; ++ky) {
#pragma unroll
            for (int kx = 0; kx < 8; ++kx) {
                int ib = ((iy0 + ky) * 84 + ix0 + kx) * 3;
                const float* wp = s_w + (ky * 8 + kx) * 32 + ocb;
#pragma unroll
                for (int c = 0; c < 3; ++c) {
                    float v0 = s_img[ib + c], v1 = s_img[ib + 12 + c];
                    float v2 = s_img[ib + 24 + c], v3 = s_img[ib + 36 + c];
                    float w[8];
                    *(float4*)&w[0] = *(const float4*)(wp + c * 2048);
                    *(float4*)&w[4] = *(const float4*)(wp + c * 2048 + 4);
#pragma unroll
                    for (int j = 0; j < 8; ++j) {
                        acc[0][j] += v0 * w[j];
                        acc[1][j] += v1 * w[j];
                        acc[2][j] += v2 * w[j];
                        acc[3][j] += v3 * w[j];
                    }
                }
            }
        }
#pragma unroll
        for (int i = 0; i < 4; ++i) {
            float* op = out + ((size_t)n * 400 + pbase + i) * 32 + ocb;
#pragma unroll
            for (int j = 0; j < 8; ++j) op[j] = fmaxf(acc[i][j] + b1[ocb + j], 0.f);
        }
    }
}

// ---------------- conv2: 20x20x32 -> 9x9x64, k=4 s=2 ----------------
__global__ void __launch_bounds__(512) conv2_kernel(const float* __restrict__ a1,
                                                    const float* __restrict__ w2,
                                                    const float* __restrict__ b2,
                                                    float* __restrict__ out) {
    extern __shared__ float sm[];
    float* s_in = sm;            // 13200 (pixel stride 33)
    float* s_w  = sm + 13200;    // 32768 [(c*16+ky*4+kx)*64 + oc]
    const int n = blockIdx.x, tid = threadIdx.x;
    const float* ip = a1 + (size_t)n * 12800;
    for (int i = tid; i < 12800; i += 512) {
        int px = i >> 5, c = i & 31;
        s_in[px * 33 + c] = ip[i];
    }
    for (int i = tid; i < 32768; i += 512) {
        int oc = i >> 9, r = i & 511;
        s_w[r * 64 + oc] = w2[i];
    }
    __syncthreads();
    const int ocb = (tid & 7) * 8;
    const int pq = tid >> 3;           // 0..63
    int p0 = pq, p1 = pq + 64;
    bool ok1 = (p1 < 81);
    int oy0 = p0 / 9, ox0 = p0 - oy0 * 9;
    int oy1 = ok1 ? p1 / 9 : oy0;
    int ox1 = ok1 ? p1 - oy1 * 9 : ox0;
    float acc0[8], acc1[8];
#pragma unroll
    for (int j = 0; j < 8; ++j) { acc0[j] = 0.f; acc1[j] = 0.f; }
    for (int ky = 0; ky < 4; ++ky) {
#pragma unroll
        for (int kx = 0; kx < 4; ++kx) {
            const float* i0 = s_in + ((oy0 * 2 + ky) * 20 + ox0 * 2 + kx) * 33;
            const float* i1 = s_in + ((oy1 * 2 + ky) * 20 + ox1 * 2 + kx) * 33;
            const float* wp = s_w + (ky * 4 + kx) * 64 + ocb;
#pragma unroll 8
            for (int c = 0; c < 32; ++c) {
                float x0 = i0[c], x1 = i1[c];
                float w[8];
                *(float4*)&w[0] = *(const float4*)(wp + c * 1024);
                *(float4*)&w[4] = *(const float4*)(wp + c * 1024 + 4);
#pragma unroll
                for (int j = 0; j < 8; ++j) {
                    acc0[j] += x0 * w[j];
                    acc1[j] += x1 * w[j];
                }
            }
        }
    }
    float* op0 = out + ((size_t)n * 81 + p0) * 64 + ocb;
#pragma unroll
    for (int j = 0; j < 8; ++j) op0[j] = fmaxf(acc0[j] + b2[ocb + j], 0.f);
    if (ok1) {
        float* op1 = out + ((size_t)n * 81 + p1) * 64 + ocb;
#pragma unroll
        for (int j = 0; j < 8; ++j) op1[j] = fmaxf(acc1[j] + b2[ocb + j], 0.f);
    }
}

// ---------------- conv3: 9x9x64 -> 7x7x64, k=3 s=1 (2 images/block) ----------------
__global__ void __launch_bounds__(512) conv3_kernel(const float* __restrict__ a2,
                                                    const float* __restrict__ w3,
                                                    const float* __restrict__ b3,
                                                    float* __restrict__ out) {
    extern __shared__ float sm[];
    float* s_in0 = sm;            // 5268 (pixel stride 65)
    float* s_in1 = sm + 5268;
    float* s_w   = sm + 10536;    // 36864 [(c*9+ky*3+kx)*64 + oc]
    const int n0 = blockIdx.x * 2, tid = threadIdx.x;
    const float* ip0 = a2 + (size_t)n0 * 5184;
    const float* ip1 = ip0 + 5184;
    for (int i = tid; i < 5184; i += 512) {
        int px = i >> 6, c = i & 63;
        s_in0[px * 65 + c] = ip0[i];
        s_in1[px * 65 + c] = ip1[i];
    }
    for (int i = tid; i < 36864; i += 512) {
        int oc = i / 576, r = i - oc * 576;
        s_w[r * 64 + oc] = w3[i];
    }
    __syncthreads();
    const int ocb = (tid & 7) * 8;
    const int p = tid >> 3;
    if (p >= 49) return;
    int oy = p / 7, ox = p - oy * 7;
    float acc0[8], acc1[8];
#pragma unroll
    for (int j = 0; j < 8; ++j) { acc0[j] = 0.f; acc1[j] = 0.f; }
#pragma unroll
    for (int ky = 0; ky < 3; ++ky) {
#pragma unroll
        for (int kx = 0; kx < 3; ++kx) {
            const float* i0 = s_in0 + ((oy + ky) * 9 + ox + kx) * 65;
            const float* i1 = s_in1 + ((oy + ky) * 9 + ox + kx) * 65;
            const float* wp = s_w + (ky * 3 + kx) * 64 + ocb;
#pragma unroll 8
            for (int c = 0; c < 64; ++c) {
                float x0 = i0[c], x1 = i1[c];
                float w[8];
                *(float4*)&w[0] = *(const float4*)(wp + c * 576);
                *(float4*)&w[4] = *(const float4*)(wp + c * 576 + 4);
#pragma unroll
                for (int j = 0; j < 8; ++j) {
                    acc0[j] += x0 * w[j];
                    acc1[j] += x1 * w[j];
                }
            }
        }
    }
    float* o0 = out + (size_t)n0 * 3136;
    float* o1 = o0 + 3136;
#pragma unroll
    for (int j = 0; j < 8; ++j) {
        o0[(ocb + j) * 49 + p] = fmaxf(acc0[j] + b3[ocb + j], 0.f);
        o1[(ocb + j) * 49 + p] = fmaxf(acc1[j] + b3[ocb + j], 0.f);
    }
}

// ---------------- generic tiled GEMM: C[M,N] (+)= A[M,K] @ B[K,N] ----------------
// BM=64, BN=128, BK=16, 256 threads, 4x8 register tile. blockIdx.z = K-split.
__global__ void __launch_bounds__(256) gemm_kernel(const float* __restrict__ A, int lda,
                                                   const float* __restrict__ B, int ldb,
                                                   float* __restrict__ C,
                                                   int M, int N, int K, int ksteps,
                                                   const float* __restrict__ bias,
                                                   int dorelu) {
    __shared__ float As[16][68];
    __shared__ float Bs[16][128];
    const int bm = blockIdx.y * 64, bn = blockIdx.x * 128;
    const int z = blockIdx.z;
    const int kbeg = z * ksteps * 16;
    const int kend = min(K, kbeg + ksteps * 16);
    C += (size_t)z * M * N;
    const int tid = threadIdx.x;
    const int tr = tid >> 4, tn = tid & 15;
    float acc[4][8];
#pragma unroll
    for (int i = 0; i < 4; ++i)
#pragma unroll
        for (int j = 0; j < 8; ++j) acc[i][j] = 0.f;
    for (int k0 = kbeg; k0 < kend; k0 += 16) {
        __syncthreads();
#pragma unroll
        for (int i = 0; i < 4; ++i) {
            int e = tid + i * 256;
            int m = e >> 4, kk = e & 15;
            As[kk][m] = A[(size_t)(bm + m) * lda + k0 + kk];
        }
#pragma unroll
        for (int i = 0; i < 8; ++i) {
            int e = tid + i * 256;
            int kk = e >> 7, nn = e & 127;
            Bs[kk][nn] = B[(size_t)(k0 + kk) * ldb + bn + nn];
        }
        __syncthreads();
#pragma unroll
        for (int kk = 0; kk < 16; ++kk) {
            float a[4], b[8];
            *(float4*)&a[0] = *(const float4*)&As[kk][tr * 4];
            *(float4*)&b[0] = *(const float4*)&Bs[kk][tn * 8];
            *(float4*)&b[4] = *(const float4*)&Bs[kk][tn * 8 + 4];
#pragma unroll
            for (int i = 0; i < 4; ++i)
#pragma unroll
                for (int j = 0; j < 8; ++j) acc[i][j] += a[i] * b[j];
        }
    }
#pragma unroll
    for (int i = 0; i < 4; ++i) {
        int m = bm + tr * 4 + i;
        float* cp = C + (size_t)m * N + bn + tn * 8;
#pragma unroll
        for (int j = 0; j < 8; ++j) {
            float v = acc[i][j];
            if (bias) v += bias[bn + tn * 8 + j];
            if (dorelu) v = fmaxf(v, 0.f);
            cp[j] = v;
        }
    }
}

// ---------------- wfeat = g_h @ Ww + bw  (2048 x 32, K=512) ----------------
__global__ void __launch_bounds__(256) wfeat_kernel(const float* __restrict__ Ww,
                                                    const float* __restrict__ bw) {
    int t = blockIdx.x * 256 + threadIdx.x;   // 65536
    int n = t >> 5, oc = t & 31;
    const float* hrow = g_h + (size_t)n * 512;
    float s = bw[oc];
#pragma unroll 8
    for (int k = 0; k < 512; ++k) s += hrow[k] * Ww[k * 32 + oc];
    g_wfeat[t] = s;
}

// ---------------- sequential scan over T=32; state in registers ----------------
__global__ void __launch_bounds__(256) scan_kernel(const float* __restrict__ done,
                                                   const float* __restrict__ state0,
                                                   const int* __restrict__ position,
                                                   float* __restrict__ out_state) {
    const int b = blockIdx.x, j = threadIdx.x;   // j = y*16+x
    float st[32];
#pragma unroll
    for (int c = 0; c < 32; ++c) st[c] = state0[b * 8192 + c * 256 + j];
    for (int t = 0; t < 32; ++t) {
        int idx = t * 64 + b;
        float m = 1.0f - done[idx];
#pragma unroll
        for (int c = 0; c < 32; ++c) st[c] *= m;
        int p0 = position[idx * 2], p1 = position[idx * 2 + 1];
        if (j == p0 * 16 + p1) {
#pragma unroll
            for (int c = 0; c < 32; ++c) st[c] += g_wfeat[idx * 32 + c];
        }
        float* hrow = g_hidden + (size_t)idx * 8256;
#pragma unroll
        for (int c = 0; c < 32; ++c) hrow[c * 256 + j] = st[c];
    }
#pragma unroll
    for (int c = 0; c < 32; ++c) out_state[b * 8192 + c * 256 + j] = st[c];
}

// ---------------- pos_net: one-hot MLP -> hidden cols 8192..8255 ----------------
__global__ void __launch_bounds__(64) posnet_kernel(const int* __restrict__ position,
                                                    const float* __restrict__ wp1,
                                                    const float* __restrict__ bp1,
                                                    const float* __restrict__ wp2,
                                                    const float* __restrict__ bp2) {
    __shared__ float hr[64];
    const int n = blockIdx.x, k = threadIdx.x;
    int p0 = position[n * 2], p1 = position[n * 2 + 1];
    hr[k] = fmaxf(wp1[p0 * 64 + k] + wp1[(16 + p1) * 64 + k] + bp1[k], 0.f);
    __syncthreads();
    float s = bp2[k];
#pragma unroll 8
    for (int j = 0; j < 64; ++j) s += hr[j] * wp2[j * 64 + k];
    g_hidden[(size_t)n * 8256 + 8192 + k] = s;
}

// ---------------- concat [wpo1 | wv1] ----------------
__global__ void wcat_kernel(const float* __restrict__ wpo1, const float* __restrict__ wv1) {
    int i = blockIdx.x * blockDim.x + threadIdx.x;
    if (i >= 8256 * 128) return;
    int k = i >> 7, nn = i & 127;
    g_w1cat[i] = (nn < 64) ? wpo1[k * 64 + nn] : wv1[k * 64 + nn - 64];
}

// ---------------- reduce split-K partials + bias + relu ----------------
__global__ void reduce_kernel(const float* __restrict__ bpo1, const float* __restrict__ bv1) {
    int i = blockIdx.x * blockDim.x + threadIdx.x;
    if (i >= 2048 * 128) return;
    float s = 0.f;
#pragma unroll
    for (int ss = 0; ss < 6; ++ss) s += g_part[ss * 262144 + i];
    int nn = i & 127;
    s += (nn < 64) ? bpo1[nn] : bv1[nn - 64];
    g_z[i] = fmaxf(s, 0.f);
}

// ---------------- heads: logits + value ----------------
__global__ void heads_kernel(const float* __restrict__ wpo2, const float* __restrict__ bpo2,
                             const float* __restrict__ wv2, const float* __restrict__ bv2,
                             float* __restrict__ out_logits, float* __restrict__ out_v) {
    int n = blockIdx.x * blockDim.x + threadIdx.x;
    if (n >= 2048) return;
    const float* z = g_z + (size_t)n * 128;
    float lg[5];
#pragma unroll
    for (int a = 0; a < 5; ++a) lg[a] = bpo2[a];
    float vv = bv2[0];
#pragma unroll 4
    for (int j = 0; j < 64; ++j) {
        float zj = z[j];
#pragma unroll
        for (int a = 0; a < 5; ++a) lg[a] += zj * wpo2[j * 5 + a];
        vv += z[64 + j] * wv2[j];
    }
#pragma unroll
    for (int a = 0; a < 5; ++a) out_logits[n * 5 + a] = lg[a];
    out_v[n] = vv;
}

// ---------------- launch ----------------
extern "C" void kernel_launch(void* const* d_in, const int* in_sizes, int n_in,
                              void* d_out, int out_size) {
    // Input ordering: setup_inputs dict order has position (int32, 4096 elems) at
    // index 3 and w1 (6144) at 4; reference-signature order has w1 at 3, position at 25.
    bool dict_order = (in_sizes[3] == 4096 && in_sizes[4] == 6144);
    int wb = dict_order ? 4 : 3;
    int posIdx = dict_order ? 3 : 25;

    const float* image  = (const float*)d_in[0];
    const float* done   = (const float*)d_in[1];
    const float* state0 = (const float*)d_in[2];
    const int*   position = (const int*)d_in[posIdx];
    const float* w1  = (const float*)d_in[wb + 0];
    const float* b1  = (const float*)d_in[wb + 1];
    const float* w2  = (const float*)d_in[wb + 2];
    const float* b2  = (const float*)d_in[wb + 3];
    const float* w3  = (const float*)d_in[wb + 4];
    const float* b3  = (const float*)d_in[wb + 5];
    const float* wfc = (const float*)d_in[wb + 6];
    const float* bfc = (const float*)d_in[wb + 7];
    const float* Ww  = (const float*)d_in[wb + 8];
    const float* bw  = (const float*)d_in[wb + 9];
    const float* wp1 = (const float*)d_in[wb + 10];
    const float* bp1 = (const float*)d_in[wb + 11];
    const float* wp2 = (const float*)d_in[wb + 12];
    const float* bp2 = (const float*)d_in[wb + 13];
    const float* wpo1 = (const float*)d_in[wb + 14];
    const float* bpo1 = (const float*)d_in[wb + 15];
    const float* wpo2 = (const float*)d_in[wb + 16];
    const float* bpo2 = (const float*)d_in[wb + 17];
    const float* wv1 = (const float*)d_in[wb + 18];
    const float* bv1 = (const float*)d_in[wb + 19];
    const float* wv2 = (const float*)d_in[wb + 20];
    const float* bv2 = (const float*)d_in[wb + 21];

    float* out = (float*)d_out;
    float* out_logits = out;               // 2048*5
    float* out_v      = out + 10240;       // 2048
    float* out_state  = out + 12288;       // 64*32*16*16

    float *p_a1, *p_a2, *p_a3, *p_h, *p_hidden, *p_w1cat, *p_part;
    cudaGetSymbolAddress((void**)&p_a1, g_a1);
    cudaGetSymbolAddress((void**)&p_a2, g_a2);
    cudaGetSymbolAddress((void**)&p_a3, g_a3);
    cudaGetSymbolAddress((void**)&p_h, g_h);
    cudaGetSymbolAddress((void**)&p_hidden, g_hidden);
    cudaGetSymbolAddress((void**)&p_w1cat, g_w1cat);
    cudaGetSymbolAddress((void**)&p_part, g_part);

    cudaFuncSetAttribute(conv1_kernel, cudaFuncAttributeMaxDynamicSharedMemorySize, 109248);
    cudaFuncSetAttribute(conv2_kernel, cudaFuncAttributeMaxDynamicSharedMemorySize, 183872);
    cudaFuncSetAttribute(conv3_kernel, cudaFuncAttributeMaxDynamicSharedMemorySize, 189600);

    conv1_kernel<<<2048, 256, 109248>>>(image, w1, b1, p_a1);
    conv2_kernel<<<2048, 512, 183872>>>(p_a1, w2, b2, p_a2);
    conv3_kernel<<<1024, 512, 189600>>>(p_a2, w3, b3, p_a3);
    // h = relu(a3 @ wfc + bfc): M=2048 N=512 K=3136
    gemm_kernel<<<dim3(4, 32, 1), 256>>>(p_a3, 3136, wfc, 512, p_h,
                                         2048, 512, 3136, 196, bfc, 1);
    wfeat_kernel<<<256, 256>>>(Ww, bw);
    scan_kernel<<<64, 256>>>(done, state0, position, out_state);
    posnet_kernel<<<2048, 64>>>(position, wp1, bp1, wp2, bp2);
    wcat_kernel<<<(8256 * 128 + 511) / 512, 512>>>(wpo1, wv1);
    // Z_partials = hidden @ [wpo1|wv1]: M=2048 N=128 K=8256, split-K=6 (1376 each)
    gemm_kernel<<<dim3(1, 32, 6), 256>>>(p_hidden, 8256, p_w1cat, 128, p_part,
                                         2048, 128, 8256, 86, (const float*)0, 0);
    reduce_kernel<<<512, 512>>>(bpo1, bv1);
    heads_kernel<<<16, 128>>>(wpo2, bpo2, wv2, bv2, out_logits, out_v);
}

// round 2
// speedup vs baseline: 1.3861x; 1.3861x over previous
#include <cuda_runtime.h>

// ---------------- scratch (device globals; no allocation allowed) ----------------
__device__ float g_a1[2048 * 400 * 32];     // conv1 out [n][p=y*20+x][c]
__device__ float g_a2[2048 * 81 * 64];      // conv2 out [n][p=y*9+x][c]
__device__ float g_a3[2048 * 3136];         // conv3 out [n][c*49+p]  (k-major for FC)
__device__ float g_h[2048 * 512];           // CNN feature
__device__ float g_wfeat[2048 * 32];        // h @ Ww + bw
__device__ float g_hidden[2048 * 8256];     // [map readout 8192 | pos_feat 64]
__device__ float g_w1cat[8256 * 128];       // [wpo1 | wv1]
__device__ float g_part[6 * 2048 * 128];    // split-K partials
__device__ float g_z[2048 * 128];           // relu(hidden@W1 + b1)
__device__ float g_w1t[6144];               // conv1 weights [r*32+oc]
__device__ float g_w2t[32768];              // conv2 weights [r*64+oc]
__device__ float g_w3t[36864];              // conv3 weights [r*64+oc]

// ---------------- packed f32x2 helpers (B300 FFMA2 path) ----------------
__device__ __forceinline__ unsigned long long pk2(float x) {
    unsigned long long r;
    unsigned u = __float_as_uint(x);
    asm("mov.b64 %0, {%1, %1};" : "=l"(r) : "r"(u));
    return r;
}
__device__ __forceinline__ void fma2(unsigned long long& d, unsigned long long a,
                                     unsigned long long b) {
    asm("fma.rn.f32x2 %0, %1, %2, %0;" : "+l"(d) : "l"(a), "l"(b));
}
__device__ __forceinline__ float2 up2(unsigned long long v) {
    unsigned lo, hi;
    asm("mov.b64 {%0, %1}, %2;" : "=r"(lo), "=r"(hi) : "l"(v));
    return make_float2(__uint_as_float(lo), __uint_as_float(hi));
}

// ---------------- prep: weight transposes + [wpo1|wv1] concat ----------------
__global__ void prep_kernel(const float* __restrict__ w1, const float* __restrict__ w2,
                            const float* __restrict__ w3, const float* __restrict__ wpo1,
                            const float* __restrict__ wv1) {
    int i = blockIdx.x * blockDim.x + threadIdx.x;
    if (i < 6144) { int oc = i / 192, r = i - oc * 192; g_w1t[r * 32 + oc] = w1[i]; }
    if (i < 32768) { int oc = i >> 9, r = i & 511; g_w2t[r * 64 + oc] = w2[i]; }
    if (i < 36864) { int oc = i / 576, r = i - oc * 576; g_w3t[r * 64 + oc] = w3[i]; }
    if (i < 8256 * 128) {
        int k = i >> 7, nn = i & 127;
        g_w1cat[i] = (nn < 64) ? wpo1[k * 64 + nn] : wv1[k * 64 + nn - 64];
    }
}

// ---------------- conv1: 84x84x3 -> 20x20x32, k=8 s=4, fused /255 ----------------
__global__ void __launch_bounds__(256) conv1_kernel(const float* __restrict__ img,
                                                    const float* __restrict__ w1t,
                                                    const float* __restrict__ b1,
                                                    float* __restrict__ out) {
    extern __shared__ float sm[];
    float* s_img = sm;            // 21168  [y][x][c]
    float* s_w   = sm + 21168;    // 6144   [(c*64+ky*8+kx)*32 + oc]
    const int n = blockIdx.x, tid = threadIdx.x;
    const float4* ip = (const float4*)(img + (size_t)n * 21168);
    for (int i = tid; i < 5292; i += 256) {
        float4 v = ip[i];
        v.x *= (1.f / 255.f); v.y *= (1.f / 255.f);
        v.z *= (1.f / 255.f); v.w *= (1.f / 255.f);
        ((float4*)s_img)[i] = v;
    }
    for (int i = tid; i < 1536; i += 256) ((float4*)s_w)[i] = ((const float4*)w1t)[i];
    __syncthreads();
    const int ocb = (tid & 3) * 8;
    const int pq = tid >> 2;
    float4 bias0 = *(const float4*)(b1 + ocb);
    float4 bias1 = *(const float4*)(b1 + ocb + 4);
    for (int it = 0; it < 2; ++it) {
        int pbase = it * 256 + pq * 4;
        if (pbase >= 400) break;
        int oy = pbase / 20, ox0 = pbase - oy * 20;
        int iy0 = oy * 4, ix0 = ox0 * 4;
        unsigned long long acc[4][4];
#pragma unroll
        for (int i = 0; i < 4; ++i)
#pragma unroll
            for (int j = 0; j < 4; ++j) acc[i][j] = 0ull;
        for (int ky = 0; ky < 8; ++ky) {
#pragma unroll
            for (int kx = 0; kx < 8; ++kx) {
                int ib = ((iy0 + ky) * 84 + ix0 + kx) * 3;
                const float* wp = s_w + (ky * 8 + kx) * 32 + ocb;
#pragma unroll
                for (int c = 0; c < 3; ++c) {
                    unsigned long long v0 = pk2(s_img[ib + c]);
                    unsigned long long v1 = pk2(s_img[ib + 12 + c]);
                    unsigned long long v2 = pk2(s_img[ib + 24 + c]);
                    unsigned long long v3 = pk2(s_img[ib + 36 + c]);
                    const ulonglong2* wq = (const ulonglong2*)(wp + c * 2048);
                    ulonglong2 wa = wq[0], wb = wq[1];
                    fma2(acc[0][0], v0, wa.x); fma2(acc[0][1], v0, wa.y);
                    fma2(acc[0][2], v0, wb.x); fma2(acc[0][3], v0, wb.y);
                    fma2(acc[1][0], v1, wa.x); fma2(acc[1][1], v1, wa.y);
                    fma2(acc[1][2], v1, wb.x); fma2(acc[1][3], v1, wb.y);
                    fma2(acc[2][0], v2, wa.x); fma2(acc[2][1], v2, wa.y);
                    fma2(acc[2][2], v2, wb.x); fma2(acc[2][3], v2, wb.y);
                    fma2(acc[3][0], v3, wa.x); fma2(acc[3][1], v3, wa.y);
                    fma2(acc[3][2], v3, wb.x); fma2(acc[3][3], v3, wb.y);
                }
            }
        }
#pragma unroll
        for (int i = 0; i < 4; ++i) {
            float2 p0 = up2(acc[i][0]), p1 = up2(acc[i][1]);
            float2 p2 = up2(acc[i][2]), p3 = up2(acc[i][3]);
            float4 o0, o1;
            o0.x = fmaxf(p0.x + bias0.x, 0.f); o0.y = fmaxf(p0.y + bias0.y, 0.f);
            o0.z = fmaxf(p1.x + bias0.z, 0.f); o0.w = fmaxf(p1.y + bias0.w, 0.f);
            o1.x = fmaxf(p2.x + bias1.x, 0.f); o1.y = fmaxf(p2.y + bias1.y, 0.f);
            o1.z = fmaxf(p3.x + bias1.z, 0.f); o1.w = fmaxf(p3.y + bias1.w, 0.f);
            float* op = out + ((size_t)n * 400 + pbase + i) * 32 + ocb;
            *(float4*)op = o0;
            *(float4*)(op + 4) = o1;
        }
    }
}

// ---------------- conv2: 20x20x32 -> 9x9x64, k=4 s=2 ----------------
__global__ void __launch_bounds__(512) conv2_kernel(const float* __restrict__ a1,
                                                    const float* __restrict__ w2t,
                                                    const float* __restrict__ b2,
                                                    float* __restrict__ out) {
    extern __shared__ float sm[];
    float* s_in = sm;            // 400*36 = 14400 (pixel stride 36)
    float* s_w  = sm + 14400;    // 32768 [(c*16+ky*4+kx)*64 + oc]
    const int n = blockIdx.x, tid = threadIdx.x;
    const float4* ip = (const float4*)(a1 + (size_t)n * 12800);
    for (int i = tid; i < 3200; i += 512) {
        int px = i >> 3, cq = i & 7;
        *(float4*)&s_in[px * 36 + cq * 4] = ip[i];
    }
    for (int i = tid; i < 8192; i += 512) ((float4*)s_w)[i] = ((const float4*)w2t)[i];
    __syncthreads();
    const int ocb = (tid & 7) * 8;
    const int pq = tid >> 3;           // 0..63
    int p0 = pq, p1 = pq + 64;
    bool ok1 = (p1 < 81);
    int oy0 = p0 / 9, ox0 = p0 - oy0 * 9;
    int oy1 = ok1 ? p1 / 9 : oy0;
    int ox1 = ok1 ? p1 - oy1 * 9 : ox0;
    unsigned long long a0[4], a1c[4];
#pragma unroll
    for (int j = 0; j < 4; ++j) { a0[j] = 0ull; a1c[j] = 0ull; }
    for (int ky = 0; ky < 4; ++ky) {
#pragma unroll
        for (int kx = 0; kx < 4; ++kx) {
            const float* i0 = s_in + ((oy0 * 2 + ky) * 20 + ox0 * 2 + kx) * 36;
            const float* i1 = s_in + ((oy1 * 2 + ky) * 20 + ox1 * 2 + kx) * 36;
            const float* wp = s_w + (ky * 4 + kx) * 64 + ocb;
#pragma unroll
            for (int c = 0; c < 32; ++c) {
                unsigned long long x0 = pk2(i0[c]);
                unsigned long long x1 = pk2(i1[c]);
                const ulonglong2* wq = (const ulonglong2*)(wp + c * 1024);
                ulonglong2 wa = wq[0], wb = wq[1];
                fma2(a0[0], x0, wa.x); fma2(a0[1], x0, wa.y);
                fma2(a0[2], x0, wb.x); fma2(a0[3], x0, wb.y);
                fma2(a1c[0], x1, wa.x); fma2(a1c[1], x1, wa.y);
                fma2(a1c[2], x1, wb.x); fma2(a1c[3], x1, wb.y);
            }
        }
    }
    float4 bias0 = *(const float4*)(b2 + ocb);
    float4 bias1 = *(const float4*)(b2 + ocb + 4);
    {
        float2 p0f = up2(a0[0]), p1f = up2(a0[1]), p2f = up2(a0[2]), p3f = up2(a0[3]);
        float4 o0, o1;
        o0.x = fmaxf(p0f.x + bias0.x, 0.f); o0.y = fmaxf(p0f.y + bias0.y, 0.f);
        o0.z = fmaxf(p1f.x + bias0.z, 0.f); o0.w = fmaxf(p1f.y + bias0.w, 0.f);
        o1.x = fmaxf(p2f.x + bias1.x, 0.f); o1.y = fmaxf(p2f.y + bias1.y, 0.f);
        o1.z = fmaxf(p3f.x + bias1.z, 0.f); o1.w = fmaxf(p3f.y + bias1.w, 0.f);
        float* op = out + ((size_t)n * 81 + p0) * 64 + ocb;
        *(float4*)op = o0; *(float4*)(op + 4) = o1;
    }
    if (ok1) {
        float2 p0f = up2(a1c[0]), p1f = up2(a1c[1]), p2f = up2(a1c[2]), p3f = up2(a1c[3]);
        float4 o0, o1;
        o0.x = fmaxf(p0f.x + bias0.x, 0.f); o0.y = fmaxf(p0f.y + bias0.y, 0.f);
        o0.z = fmaxf(p1f.x + bias0.z, 0.f); o0.w = fmaxf(p1f.y + bias0.w, 0.f);
        o1.x = fmaxf(p2f.x + bias1.x, 0.f); o1.y = fmaxf(p2f.y + bias1.y, 0.f);
        o1.z = fmaxf(p3f.x + bias1.z, 0.f); o1.w = fmaxf(p3f.y + bias1.w, 0.f);
        float* op = out + ((size_t)n * 81 + p1) * 64 + ocb;
        *(float4*)op = o0; *(float4*)(op + 4) = o1;
    }
}

// ---------------- conv3: 9x9x64 -> 7x7x64, k=3 s=1 (2 images/block) ----------------
__global__ void __launch_bounds__(512) conv3_kernel(const float* __restrict__ a2,
                                                    const float* __restrict__ w3t,
                                                    const float* __restrict__ b3,
                                                    float* __restrict__ out) {
    extern __shared__ float sm[];
    float* s_in0 = sm;            // 81*68 = 5508
    float* s_in1 = sm + 5508;
    float* s_w   = sm + 11016;    // 36864 [(c*9+ky*3+kx)*64 + oc]
    const int n0 = blockIdx.x * 2, tid = threadIdx.x;
    const float4* ip0 = (const float4*)(a2 + (size_t)n0 * 5184);
    const float4* ip1 = (const float4*)(a2 + (size_t)(n0 + 1) * 5184);
    for (int i = tid; i < 1296; i += 512) {
        int px = i >> 4, cq = i & 15;
        *(float4*)&s_in0[px * 68 + cq * 4] = ip0[i];
        *(float4*)&s_in1[px * 68 + cq * 4] = ip1[i];
    }
    for (int i = tid; i < 9216; i += 512) ((float4*)s_w)[i] = ((const float4*)w3t)[i];
    __syncthreads();
    const int ocb = (tid & 7) * 8;
    const int p = tid >> 3;
    if (p >= 49) return;
    int oy = p / 7, ox = p - oy * 7;
    unsigned long long a0[4], a1c[4];
#pragma unroll
    for (int j = 0; j < 4; ++j) { a0[j] = 0ull; a1c[j] = 0ull; }
#pragma unroll
    for (int ky = 0; ky < 3; ++ky) {
#pragma unroll
        for (int kx = 0; kx < 3; ++kx) {
            const float* i0 = s_in0 + ((oy + ky) * 9 + ox + kx) * 68;
            const float* i1 = s_in1 + ((oy + ky) * 9 + ox + kx) * 68;
            const float* wp = s_w + (ky * 3 + kx) * 64 + ocb;
#pragma unroll
            for (int c = 0; c < 64; ++c) {
                unsigned long long x0 = pk2(i0[c]);
                unsigned long long x1 = pk2(i1[c]);
                const ulonglong2* wq = (const ulonglong2*)(wp + c * 576);
                ulonglong2 wa = wq[0], wb = wq[1];
                fma2(a0[0], x0, wa.x); fma2(a0[1], x0, wa.y);
                fma2(a0[2], x0, wb.x); fma2(a0[3], x0, wb.y);
                fma2(a1c[0], x1, wa.x); fma2(a1c[1], x1, wa.y);
                fma2(a1c[2], x1, wb.x); fma2(a1c[3], x1, wb.y);
            }
        }
    }
    float* o0 = out + (size_t)n0 * 3136;
    float* o1 = o0 + 3136;
#pragma unroll
    for (int j = 0; j < 4; ++j) {
        float2 q0 = up2(a0[j]), q1 = up2(a1c[j]);
        int oc0 = ocb + j * 2, oc1 = ocb + j * 2 + 1;
        o0[oc0 * 49 + p] = fmaxf(q0.x + b3[oc0], 0.f);
        o0[oc1 * 49 + p] = fmaxf(q0.y + b3[oc1], 0.f);
        o1[oc0 * 49 + p] = fmaxf(q1.x + b3[oc0], 0.f);
        o1[oc1 * 49 + p] = fmaxf(q1.y + b3[oc1], 0.f);
    }
}

// ---------------- tiled GEMM: C[M,N] = A[M,K] @ B[K,N], BM=BN=64, BK=16 ----------------
// 256 threads, 4x4/thread via FFMA2, double-buffered smem. blockIdx.z = K-split.
__global__ void __launch_bounds__(256) gemm_kernel(const float* __restrict__ A, int lda,
                                                   const float* __restrict__ B, int ldb,
                                                   float* __restrict__ C,
                                                   int M, int N, int K, int ksteps,
                                                   const float* __restrict__ bias,
                                                   int dorelu) {
    __shared__ __align__(16) float As[2][16][68];
    __shared__ __align__(16) float Bs[2][16][64];
    const int bm = blockIdx.y * 64, bn = blockIdx.x * 64;
    const int z = blockIdx.z;
    const int kbeg = z * ksteps * 16;
    const int kend = min(K, kbeg + ksteps * 16);
    C += (size_t)z * M * N;
    const int tid = threadIdx.x;
    const int tr = tid >> 4, tc = tid & 15;
    const int am = tid >> 2, ak = (tid & 3) * 4;
    const int bk = tid >> 4, bn4 = (tid & 15) * 4;
    unsigned long long acc[4][2];
#pragma unroll
    for (int i = 0; i < 4; ++i) { acc[i][0] = 0ull; acc[i][1] = 0ull; }
    const float* Aptr = A + (size_t)(bm + am) * lda + ak;
    const float* Bptr = B + (size_t)bk * ldb + bn + bn4;
    float4 ra = *(const float4*)(Aptr + kbeg);
    float4 rb = *(const float4*)(Bptr + (size_t)kbeg * ldb);
    As[0][ak + 0][am] = ra.x; As[0][ak + 1][am] = ra.y;
    As[0][ak + 2][am] = ra.z; As[0][ak + 3][am] = ra.w;
    *(float4*)&Bs[0][bk][bn4] = rb;
    __syncthreads();
    int cur = 0;
    for (int k0 = kbeg; k0 < kend; k0 += 16) {
        bool more = (k0 + 16) < kend;
        if (more) {
            ra = *(const float4*)(Aptr + k0 + 16);
            rb = *(const float4*)(Bptr + (size_t)(k0 + 16) * ldb);
        }
#pragma unroll
        for (int kk = 0; kk < 16; ++kk) {
            float4 av = *(const float4*)&As[cur][kk][tr * 4];
            ulonglong2 bv = *(const ulonglong2*)&Bs[cur][kk][tc * 4];
            unsigned long long a0 = pk2(av.x), a1 = pk2(av.y);
            unsigned long long a2 = pk2(av.z), a3 = pk2(av.w);
            fma2(acc[0][0], a0, bv.x); fma2(acc[0][1], a0, bv.y);
            fma2(acc[1][0], a1, bv.x); fma2(acc[1][1], a1, bv.y);
            fma2(acc[2][0], a2, bv.x); fma2(acc[2][1], a2, bv.y);
            fma2(acc[3][0], a3, bv.x); fma2(acc[3][1], a3, bv.y);
        }
        if (more) {
            As[cur ^ 1][ak + 0][am] = ra.x; As[cur ^ 1][ak + 1][am] = ra.y;
            As[cur ^ 1][ak + 2][am] = ra.z; As[cur ^ 1][ak + 3][am] = ra.w;
            *(float4*)&Bs[cur ^ 1][bk][bn4] = rb;
        }
        __syncthreads();
        cur ^= 1;
    }
    float b0 = 0.f, b1v = 0.f, b2v = 0.f, b3v = 0.f;
    if (bias) {
        const float4 bb = *(const float4*)(bias + bn + tc * 4);
        b0 = bb.x; b1v = bb.y; b2v = bb.z; b3v = bb.w;
    }
#pragma unroll
    for (int i = 0; i < 4; ++i) {
        float2 p0 = up2(acc[i][0]), p1 = up2(acc[i][1]);
        float4 o;
        o.x = p0.x + b0; o.y = p0.y + b1v; o.z = p1.x + b2v; o.w = p1.y + b3v;
        if (dorelu) {
            o.x = fmaxf(o.x, 0.f); o.y = fmaxf(o.y, 0.f);
            o.z = fmaxf(o.z, 0.f); o.w = fmaxf(o.w, 0.f);
        }
        *(float4*)&C[(size_t)(bm + tr * 4 + i) * N + bn + tc * 4] = o;
    }
}

// ---------------- wfeat = g_h @ Ww + bw  (2048 x 32, K=512) ----------------
__global__ void __launch_bounds__(256) wfeat_kernel(const float* __restrict__ Ww,
                                                    const float* __restrict__ bw) {
    int t = blockIdx.x * 256 + threadIdx.x;   // 65536
    int n = t >> 5, oc = t & 31;
    const float* hrow = g_h + (size_t)n * 512;
    float s = bw[oc];
#pragma unroll 8
    for (int k = 0; k < 512; ++k) s += hrow[k] * Ww[k * 32 + oc];
    g_wfeat[t] = s;
}

// ---------------- sequential scan over T=32; state in registers ----------------
__global__ void __launch_bounds__(256) scan_kernel(const float* __restrict__ done,
                                                   const float* __restrict__ state0,
                                                   const int* __restrict__ position,
                                                   float* __restrict__ out_state) {
    const int b = blockIdx.x, j = threadIdx.x;   // j = y*16+x
    float st[32];
#pragma unroll
    for (int c = 0; c < 32; ++c) st[c] = state0[b * 8192 + c * 256 + j];
    for (int t = 0; t < 32; ++t) {
        int idx = t * 64 + b;
        float m = 1.0f - done[idx];
#pragma unroll
        for (int c = 0; c < 32; ++c) st[c] *= m;
        int p0 = position[idx * 2], p1 = position[idx * 2 + 1];
        if (j == p0 * 16 + p1) {
#pragma unroll
            for (int c = 0; c < 32; ++c) st[c] += g_wfeat[idx * 32 + c];
        }
        float* hrow = g_hidden + (size_t)idx * 8256;
#pragma unroll
        for (int c = 0; c < 32; ++c) hrow[c * 256 + j] = st[c];
    }
#pragma unroll
    for (int c = 0; c < 32; ++c) out_state[b * 8192 + c * 256 + j] = st[c];
}

// ---------------- pos_net: one-hot MLP -> hidden cols 8192..8255 ----------------
__global__ void __launch_bounds__(64) posnet_kernel(const int* __restrict__ position,
                                                    const float* __restrict__ wp1,
                                                    const float* __restrict__ bp1,
                                                    const float* __restrict__ wp2,
                                                    const float* __restrict__ bp2) {
    __shared__ float hr[64];
    const int n = blockIdx.x, k = threadIdx.x;
    int p0 = position[n * 2], p1 = position[n * 2 + 1];
    hr[k] = fmaxf(wp1[p0 * 64 + k] + wp1[(16 + p1) * 64 + k] + bp1[k], 0.f);
    __syncthreads();
    float s = bp2[k];
#pragma unroll 8
    for (int j = 0; j < 64; ++j) s += hr[j] * wp2[j * 64 + k];
    g_hidden[(size_t)n * 8256 + 8192 + k] = s;
}

// ---------------- reduce split-K partials + bias + relu ----------------
__global__ void reduce_kernel(const float* __restrict__ bpo1, const float* __restrict__ bv1) {
    int i = blockIdx.x * blockDim.x + threadIdx.x;
    if (i >= 2048 * 128) return;
    float s = 0.f;
#pragma unroll
    for (int ss = 0; ss < 4; ++ss) s += g_part[ss * 262144 + i];
    int nn = i & 127;
    s += (nn < 64) ? bpo1[nn] : bv1[nn - 64];
    g_z[i] = fmaxf(s, 0.f);
}

// ---------------- heads: logits + value ----------------
__global__ void heads_kernel(const float* __restrict__ wpo2, const float* __restrict__ bpo2,
                             const float* __restrict__ wv2, const float* __restrict__ bv2,
                             float* __restrict__ out_logits, float* __restrict__ out_v) {
    int n = blockIdx.x * blockDim.x + threadIdx.x;
    if (n >= 2048) return;
    const float* z = g_z + (size_t)n * 128;
    float lg[5];
#pragma unroll
    for (int a = 0; a < 5; ++a) lg[a] = bpo2[a];
    float vv = bv2[0];
#pragma unroll 4
    for (int j = 0; j < 64; ++j) {
        float zj = z[j];
#pragma unroll
        for (int a = 0; a < 5; ++a) lg[a] += zj * wpo2[j * 5 + a];
        vv += z[64 + j] * wv2[j];
    }
#pragma unroll
    for (int a = 0; a < 5; ++a) out_logits[n * 5 + a] = lg[a];
    out_v[n] = vv;
}

// ---------------- launch ----------------
extern "C" void kernel_launch(void* const* d_in, const int* in_sizes, int n_in,
                              void* d_out, int out_size) {
    bool dict_order = (in_sizes[3] == 4096 && in_sizes[4] == 6144);
    int wb = dict_order ? 4 : 3;
    int posIdx = dict_order ? 3 : 25;

    const float* image  = (const float*)d_in[0];
    const float* done   = (const float*)d_in[1];
    const float* state0 = (const float*)d_in[2];
    const int*   position = (const int*)d_in[posIdx];
    const float* w1  = (const float*)d_in[wb + 0];
    const float* b1  = (const float*)d_in[wb + 1];
    const float* w2  = (const float*)d_in[wb + 2];
    const float* b2  = (const float*)d_in[wb + 3];
    const float* w3  = (const float*)d_in[wb + 4];
    const float* b3  = (const float*)d_in[wb + 5];
    const float* wfc = (const float*)d_in[wb + 6];
    const float* bfc = (const float*)d_in[wb + 7];
    const float* Ww  = (const float*)d_in[wb + 8];
    const float* bw  = (const float*)d_in[wb + 9];
    const float* wp1 = (const float*)d_in[wb + 10];
    const float* bp1 = (const float*)d_in[wb + 11];
    const float* wp2 = (const float*)d_in[wb + 12];
    const float* bp2 = (const float*)d_in[wb + 13];
    const float* wpo1 = (const float*)d_in[wb + 14];
    const float* bpo1 = (const float*)d_in[wb + 15];
    const float* wpo2 = (const float*)d_in[wb + 16];
    const float* bpo2 = (const float*)d_in[wb + 17];
    const float* wv1 = (const float*)d_in[wb + 18];
    const float* bv1 = (const float*)d_in[wb + 19];
    const float* wv2 = (const float*)d_in[wb + 20];
    const float* bv2 = (const float*)d_in[wb + 21];

    float* out = (float*)d_out;
    float* out_logits = out;               // 2048*5
    float* out_v      = out + 10240;       // 2048
    float* out_state  = out + 12288;       // 64*32*16*16

    float *p_a1, *p_a2, *p_a3, *p_h, *p_hidden, *p_w1cat, *p_part;
    float *p_w1t, *p_w2t, *p_w3t;
    cudaGetSymbolAddress((void**)&p_a1, g_a1);
    cudaGetSymbolAddress((void**)&p_a2, g_a2);
    cudaGetSymbolAddress((void**)&p_a3, g_a3);
    cudaGetSymbolAddress((void**)&p_h, g_h);
    cudaGetSymbolAddress((void**)&p_hidden, g_hidden);
    cudaGetSymbolAddress((void**)&p_w1cat, g_w1cat);
    cudaGetSymbolAddress((void**)&p_part, g_part);
    cudaGetSymbolAddress((void**)&p_w1t, g_w1t);
    cudaGetSymbolAddress((void**)&p_w2t, g_w2t);
    cudaGetSymbolAddress((void**)&p_w3t, g_w3t);

    cudaFuncSetAttribute(conv1_kernel, cudaFuncAttributeMaxDynamicSharedMemorySize, 109248);
    cudaFuncSetAttribute(conv2_kernel, cudaFuncAttributeMaxDynamicSharedMemorySize, 188672);
    cudaFuncSetAttribute(conv3_kernel, cudaFuncAttributeMaxDynamicSharedMemorySize, 191520);

    prep_kernel<<<2064, 512>>>(w1, w2, w3, wpo1, wv1);
    conv1_kernel<<<2048, 256, 109248>>>(image, p_w1t, b1, p_a1);
    conv2_kernel<<<2048, 512, 188672>>>(p_a1, p_w2t, b2, p_a2);
    conv3_kernel<<<1024, 512, 191520>>>(p_a2, p_w3t, b3, p_a3);
    // h = relu(a3 @ wfc + bfc): M=2048 N=512 K=3136
    gemm_kernel<<<dim3(8, 32, 1), 256>>>(p_a3, 3136, wfc, 512, p_h,
                                         2048, 512, 3136, 196, bfc, 1);
    wfeat_kernel<<<256, 256>>>(Ww, bw);
    scan_kernel<<<64, 256>>>(done, state0, position, out_state);
    posnet_kernel<<<2048, 64>>>(position, wp1, bp1, wp2, bp2);
    // Z_partials = hidden @ [wpo1|wv1]: M=2048 N=128 K=8256, split-K=4 (129 steps each)
    gemm_kernel<<<dim3(2, 32, 4), 256>>>(p_hidden, 8256, p_w1cat, 128, p_part,
                                         2048, 128, 8256, 129, (const float*)0, 0);
    reduce_kernel<<<512, 512>>>(bpo1, bv1);
    heads_kernel<<<16, 128>>>(wpo2, bpo2, wv2, bv2, out_logits, out_v);
}

// round 3
// speedup vs baseline: 1.7229x; 1.2430x over previous
#include <cuda_runtime.h>

// ---------------- scratch (device globals; no allocation allowed) ----------------
__device__ float g_a1[2048 * 400 * 32];     // conv1 out [n][p=y*20+x][c]
__device__ float g_a2[2048 * 81 * 64];      // conv2 out [n][p=y*9+x][c]
__device__ float g_a3[2048 * 3136];         // conv3 out [n][c*49+p]  (k-major for FC)
__device__ float g_h[2048 * 512];           // CNN feature
__device__ float g_wfeat[2048 * 32];        // h @ Ww + bw
__device__ float g_hidden[2048 * 8256];     // [map readout 8192 | pos_feat 64]
__device__ float g_w1cat[8256 * 128];       // [wpo1 | wv1]
__device__ float g_part[6 * 2048 * 128];    // split-K partials
__device__ float g_z[2048 * 128];           // relu(hidden@W1 + b1)
__device__ float g_w1t[6144];               // conv1 weights [c*64+kykx][oc]
__device__ float g_w2t[32768];              // conv2 weights [kykx][c][oc]
__device__ float g_w3t[36864];              // conv3 weights [kykx][c][oc]

// ---------------- packed f32x2 helpers (B300 FFMA2 path) ----------------
__device__ __forceinline__ unsigned long long pk2(float x) {
    unsigned long long r;
    unsigned u = __float_as_uint(x);
    asm("mov.b64 %0, {%1, %1};" : "=l"(r) : "r"(u));
    return r;
}
__device__ __forceinline__ void fma2(unsigned long long& d, unsigned long long a,
                                     unsigned long long b) {
    asm("fma.rn.f32x2 %0, %1, %2, %0;" : "+l"(d) : "l"(a), "l"(b));
}
__device__ __forceinline__ float2 up2(unsigned long long v) {
    unsigned lo, hi;
    asm("mov.b64 {%0, %1}, %2;" : "=r"(lo), "=r"(hi) : "l"(v));
    return make_float2(__uint_as_float(lo), __uint_as_float(hi));
}

// ---------------- prep: weight transposes + [wpo1|wv1] concat ----------------
__global__ void prep_kernel(const float* __restrict__ w1, const float* __restrict__ w2,
                            const float* __restrict__ w3, const float* __restrict__ wpo1,
                            const float* __restrict__ wv1) {
    int i = blockIdx.x * blockDim.x + threadIdx.x;
    if (i < 6144) {  // w1 [oc][c][8][8] -> [c*64+kykx][oc]
        int oc = i / 192, r = i - oc * 192;
        g_w1t[r * 32 + oc] = w1[i];
    }
    if (i < 32768) { // w2 [oc][c][4][4] -> [kykx][c][oc]
        int oc = i >> 9, c = (i >> 4) & 31, kk = i & 15;
        g_w2t[(kk * 32 + c) * 64 + oc] = w2[i];
    }
    if (i < 36864) { // w3 [oc][c][3][3] -> [kykx][c][oc]
        int oc = i / 576, r = i - oc * 576, c = r / 9, kk = r - c * 9;
        g_w3t[(kk * 64 + c) * 64 + oc] = w3[i];
    }
    if (i < 8256 * 128) {
        int k = i >> 7, nn = i & 127;
        g_w1cat[i] = (nn < 64) ? wpo1[k * 64 + nn] : wv1[k * 64 + nn - 64];
    }
}

// ---------------- conv1: 84x84x3 -> 20x20x32, k=8 s=4, half image per block ----------------
__global__ void __launch_bounds__(256) conv1_kernel(const float* __restrict__ img,
                                                    const float* __restrict__ w1t,
                                                    const float* __restrict__ b1,
                                                    float* __restrict__ out) {
    extern __shared__ float sm[];
    float* s_img = sm;            // 44 rows * 252 = 11088
    float* s_w   = sm + 11088;    // 6144
    const int n = blockIdx.x >> 1, h = blockIdx.x & 1;
    const int tid = threadIdx.x;
    const float4* ip = (const float4*)(img + (size_t)n * 21168 + h * (40 * 252));
    for (int i = tid; i < 2772; i += 256) {
        float4 v = ip[i];
        v.x *= (1.f / 255.f); v.y *= (1.f / 255.f);
        v.z *= (1.f / 255.f); v.w *= (1.f / 255.f);
        ((float4*)s_img)[i] = v;
    }
    for (int i = tid; i < 1536; i += 256) ((float4*)s_w)[i] = ((const float4*)w1t)[i];
    __syncthreads();
    const int ocb = (tid & 3) * 8;
    const int pbase = (tid >> 2) * 4;     // 0..252, valid < 200
    if (pbase >= 200) return;
    float4 bias0 = *(const float4*)(b1 + ocb);
    float4 bias1 = *(const float4*)(b1 + ocb + 4);
    int oy = pbase / 20, ox0 = pbase - oy * 20;   // local oy 0..9
    int iy0 = oy * 4, ix0 = ox0 * 4;              // local input coords
    unsigned long long acc[4][4];
#pragma unroll
    for (int i = 0; i < 4; ++i)
#pragma unroll
        for (int j = 0; j < 4; ++j) acc[i][j] = 0ull;
    for (int ky = 0; ky < 8; ++ky) {
#pragma unroll
        for (int kx = 0; kx < 8; ++kx) {
            int ib = ((iy0 + ky) * 84 + ix0 + kx) * 3;
            const float* wp = s_w + (ky * 8 + kx) * 32 + ocb;
#pragma unroll
            for (int c = 0; c < 3; ++c) {
                unsigned long long v0 = pk2(s_img[ib + c]);
                unsigned long long v1 = pk2(s_img[ib + 12 + c]);
                unsigned long long v2 = pk2(s_img[ib + 24 + c]);
                unsigned long long v3 = pk2(s_img[ib + 36 + c]);
                const ulonglong2* wq = (const ulonglong2*)(wp + c * 2048);
                ulonglong2 wa = wq[0], wb = wq[1];
                fma2(acc[0][0], v0, wa.x); fma2(acc[0][1], v0, wa.y);
                fma2(acc[0][2], v0, wb.x); fma2(acc[0][3], v0, wb.y);
                fma2(acc[1][0], v1, wa.x); fma2(acc[1][1], v1, wa.y);
                fma2(acc[1][2], v1, wb.x); fma2(acc[1][3], v1, wb.y);
                fma2(acc[2][0], v2, wa.x); fma2(acc[2][1], v2, wa.y);
                fma2(acc[2][2], v2, wb.x); fma2(acc[2][3], v2, wb.y);
                fma2(acc[3][0], v3, wa.x); fma2(acc[3][1], v3, wa.y);
                fma2(acc[3][2], v3, wb.x); fma2(acc[3][3], v3, wb.y);
            }
        }
    }
#pragma unroll
    for (int i = 0; i < 4; ++i) {
        float2 p0 = up2(acc[i][0]), p1 = up2(acc[i][1]);
        float2 p2 = up2(acc[i][2]), p3 = up2(acc[i][3]);
        float4 o0, o1;
        o0.x = fmaxf(p0.x + bias0.x, 0.f); o0.y = fmaxf(p0.y + bias0.y, 0.f);
        o0.z = fmaxf(p1.x + bias0.z, 0.f); o0.w = fmaxf(p1.y + bias0.w, 0.f);
        o1.x = fmaxf(p2.x + bias1.x, 0.f); o1.y = fmaxf(p2.y + bias1.y, 0.f);
        o1.z = fmaxf(p3.x + bias1.z, 0.f); o1.w = fmaxf(p3.y + bias1.w, 0.f);
        float* op = out + ((size_t)n * 400 + h * 200 + pbase + i) * 32 + ocb;
        *(float4*)op = o0;
        *(float4*)(op + 4) = o1;
    }
}

// ---------------- conv2: 20x20x32 -> 9x9x64, k=4 s=2; weights via LDG ----------------
__global__ void __launch_bounds__(256) conv2_kernel(const float* __restrict__ a1,
                                                    const float* __restrict__ w2t,
                                                    const float* __restrict__ b2,
                                                    float* __restrict__ out) {
    extern __shared__ float sm[];
    float* s_in = sm;            // 400*36 = 14400 floats (57.6 KB)
    const int n = blockIdx.x, tid = threadIdx.x;
    const float4* ip = (const float4*)(a1 + (size_t)n * 12800);
    for (int i = tid; i < 3200; i += 256) {
        int px = i >> 3, cq = i & 7;
        *(float4*)&s_in[px * 36 + cq * 4] = ip[i];
    }
    __syncthreads();
    const int ocb = (tid & 7) * 8;
    const int pq = tid >> 3;             // 0..31
    const int p0 = pq, p1 = pq + 32, p2 = pq + 64;
    const bool ok2 = (p2 < 81);
    int oy0 = p0 / 9, ox0 = p0 - oy0 * 9;
    int oy1 = p1 / 9, ox1 = p1 - oy1 * 9;
    int oy2 = ok2 ? p2 / 9 : oy1, ox2 = ok2 ? p2 - oy2 * 9 : ox1;
    unsigned long long a0[4], a1c[4], a2c[4];
#pragma unroll
    for (int j = 0; j < 4; ++j) { a0[j] = 0ull; a1c[j] = 0ull; a2c[j] = 0ull; }
#pragma unroll
    for (int ky = 0; ky < 4; ++ky) {
#pragma unroll
        for (int kx = 0; kx < 4; ++kx) {
            const float* i0 = s_in + ((oy0 * 2 + ky) * 20 + ox0 * 2 + kx) * 36;
            const float* i1 = s_in + ((oy1 * 2 + ky) * 20 + ox1 * 2 + kx) * 36;
            const float* i2 = s_in + ((oy2 * 2 + ky) * 20 + ox2 * 2 + kx) * 36;
            const float* wb = w2t + ((ky * 4 + kx) * 32) * 64 + ocb;
#pragma unroll 4
            for (int c = 0; c < 32; ++c) {
                unsigned long long x0 = pk2(i0[c]);
                unsigned long long x1 = pk2(i1[c]);
                unsigned long long x2 = pk2(i2[c]);
                const ulonglong2* wq = (const ulonglong2*)(wb + c * 64);
                ulonglong2 wa = wq[0], wbv = wq[1];
                fma2(a0[0], x0, wa.x); fma2(a0[1], x0, wa.y);
                fma2(a0[2], x0, wbv.x); fma2(a0[3], x0, wbv.y);
                fma2(a1c[0], x1, wa.x); fma2(a1c[1], x1, wa.y);
                fma2(a1c[2], x1, wbv.x); fma2(a1c[3], x1, wbv.y);
                fma2(a2c[0], x2, wa.x); fma2(a2c[1], x2, wa.y);
                fma2(a2c[2], x2, wbv.x); fma2(a2c[3], x2, wbv.y);
            }
        }
    }
    float4 bias0 = *(const float4*)(b2 + ocb);
    float4 bias1 = *(const float4*)(b2 + ocb + 4);
    unsigned long long* accs[3] = {a0, a1c, a2c};
    int ps[3] = {p0, p1, p2};
#pragma unroll
    for (int s = 0; s < 3; ++s) {
        if (s == 2 && !ok2) break;
        float2 q0 = up2(accs[s][0]), q1 = up2(accs[s][1]);
        float2 q2 = up2(accs[s][2]), q3 = up2(accs[s][3]);
        float4 o0, o1;
        o0.x = fmaxf(q0.x + bias0.x, 0.f); o0.y = fmaxf(q0.y + bias0.y, 0.f);
        o0.z = fmaxf(q1.x + bias0.z, 0.f); o0.w = fmaxf(q1.y + bias0.w, 0.f);
        o1.x = fmaxf(q2.x + bias1.x, 0.f); o1.y = fmaxf(q2.y + bias1.y, 0.f);
        o1.z = fmaxf(q3.x + bias1.z, 0.f); o1.w = fmaxf(q3.y + bias1.w, 0.f);
        float* op = out + ((size_t)n * 81 + ps[s]) * 64 + ocb;
        *(float4*)op = o0; *(float4*)(op + 4) = o1;
    }
}

// ---------------- conv3: 9x9x64 -> 7x7x64, 2 img/block, 16 oc/thread, LDG weights ----------------
__global__ void __launch_bounds__(256) conv3_kernel(const float* __restrict__ a2,
                                                    const float* __restrict__ w3t,
                                                    const float* __restrict__ b3,
                                                    float* __restrict__ out) {
    extern __shared__ float sm[];
    float* s_in0 = sm;            // 81*68 = 5508
    float* s_in1 = sm + 5508;
    const int n0 = blockIdx.x * 2, tid = threadIdx.x;
    const float4* ip0 = (const float4*)(a2 + (size_t)n0 * 5184);
    const float4* ip1 = (const float4*)(a2 + (size_t)(n0 + 1) * 5184);
    for (int i = tid; i < 1296; i += 256) {
        int px = i >> 4, cq = i & 15;
        *(float4*)&s_in0[px * 68 + cq * 4] = ip0[i];
        *(float4*)&s_in1[px * 68 + cq * 4] = ip1[i];
    }
    __syncthreads();
    const int ocb = (tid & 3) * 16;
    const int p = tid >> 2;             // 0..63, valid < 49
    if (p >= 49) return;
    int oy = p / 7, ox = p - oy * 7;
    unsigned long long a0[8], a1c[8];
#pragma unroll
    for (int j = 0; j < 8; ++j) { a0[j] = 0ull; a1c[j] = 0ull; }
#pragma unroll
    for (int ky = 0; ky < 3; ++ky) {
#pragma unroll
        for (int kx = 0; kx < 3; ++kx) {
            const float* i0 = s_in0 + ((oy + ky) * 9 + ox + kx) * 68;
            const float* i1 = s_in1 + ((oy + ky) * 9 + ox + kx) * 68;
            const float* wb = w3t + ((ky * 3 + kx) * 64) * 64 + ocb;
#pragma unroll 4
            for (int c = 0; c < 64; ++c) {
                unsigned long long x0 = pk2(i0[c]);
                unsigned long long x1 = pk2(i1[c]);
                const ulonglong2* wq = (const ulonglong2*)(wb + c * 64);
                ulonglong2 w0 = wq[0], w1v = wq[1], w2v = wq[2], w3v = wq[3];
                fma2(a0[0], x0, w0.x);  fma2(a0[1], x0, w0.y);
                fma2(a0[2], x0, w1v.x); fma2(a0[3], x0, w1v.y);
                fma2(a0[4], x0, w2v.x); fma2(a0[5], x0, w2v.y);
                fma2(a0[6], x0, w3v.x); fma2(a0[7], x0, w3v.y);
                fma2(a1c[0], x1, w0.x);  fma2(a1c[1], x1, w0.y);
                fma2(a1c[2], x1, w1v.x); fma2(a1c[3], x1, w1v.y);
                fma2(a1c[4], x1, w2v.x); fma2(a1c[5], x1, w2v.y);
                fma2(a1c[6], x1, w3v.x); fma2(a1c[7], x1, w3v.y);
            }
        }
    }
    float* o0 = out + (size_t)n0 * 3136;
    float* o1 = o0 + 3136;
#pragma unroll
    for (int j = 0; j < 8; ++j) {
        float2 q0 = up2(a0[j]), q1 = up2(a1c[j]);
        int oc0 = ocb + j * 2, oc1 = ocb + j * 2 + 1;
        o0[oc0 * 49 + p] = fmaxf(q0.x + b3[oc0], 0.f);
        o0[oc1 * 49 + p] = fmaxf(q0.y + b3[oc1], 0.f);
        o1[oc0 * 49 + p] = fmaxf(q1.x + b3[oc0], 0.f);
        o1[oc1 * 49 + p] = fmaxf(q1.y + b3[oc1], 0.f);
    }
}

// ---------------- tiled GEMM: C[M,N] = A[M,K] @ B[K,N], BM=BN=64, BK=16 ----------------
__global__ void __launch_bounds__(256) gemm_kernel(const float* __restrict__ A, int lda,
                                                   const float* __restrict__ B, int ldb,
                                                   float* __restrict__ C,
                                                   int M, int N, int K, int ksteps,
                                                   const float* __restrict__ bias,
                                                   int dorelu) {
    __shared__ __align__(16) float As[2][16][68];
    __shared__ __align__(16) float Bs[2][16][64];
    const int bm = blockIdx.y * 64, bn = blockIdx.x * 64;
    const int z = blockIdx.z;
    const int kbeg = z * ksteps * 16;
    const int kend = min(K, kbeg + ksteps * 16);
    C += (size_t)z * M * N;
    const int tid = threadIdx.x;
    const int tr = tid >> 4, tc = tid & 15;
    const int am = tid >> 2, ak = (tid & 3) * 4;
    const int bk = tid >> 4, bn4 = (tid & 15) * 4;
    unsigned long long acc[4][2];
#pragma unroll
    for (int i = 0; i < 4; ++i) { acc[i][0] = 0ull; acc[i][1] = 0ull; }
    const float* Aptr = A + (size_t)(bm + am) * lda + ak;
    const float* Bptr = B + (size_t)bk * ldb + bn + bn4;
    float4 ra = *(const float4*)(Aptr + kbeg);
    float4 rb = *(const float4*)(Bptr + (size_t)kbeg * ldb);
    As[0][ak + 0][am] = ra.x; As[0][ak + 1][am] = ra.y;
    As[0][ak + 2][am] = ra.z; As[0][ak + 3][am] = ra.w;
    *(float4*)&Bs[0][bk][bn4] = rb;
    __syncthreads();
    int cur = 0;
    for (int k0 = kbeg; k0 < kend; k0 += 16) {
        bool more = (k0 + 16) < kend;
        if (more) {
            ra = *(const float4*)(Aptr + k0 + 16);
            rb = *(const float4*)(Bptr + (size_t)(k0 + 16) * ldb);
        }
#pragma unroll
        for (int kk = 0; kk < 16; ++kk) {
            float4 av = *(const float4*)&As[cur][kk][tr * 4];
            ulonglong2 bv = *(const ulonglong2*)&Bs[cur][kk][tc * 4];
            unsigned long long a0 = pk2(av.x), a1 = pk2(av.y);
            unsigned long long a2 = pk2(av.z), a3 = pk2(av.w);
            fma2(acc[0][0], a0, bv.x); fma2(acc[0][1], a0, bv.y);
            fma2(acc[1][0], a1, bv.x); fma2(acc[1][1], a1, bv.y);
            fma2(acc[2][0], a2, bv.x); fma2(acc[2][1], a2, bv.y);
            fma2(acc[3][0], a3, bv.x); fma2(acc[3][1], a3, bv.y);
        }
        if (more) {
            As[cur ^ 1][ak + 0][am] = ra.x; As[cur ^ 1][ak + 1][am] = ra.y;
            As[cur ^ 1][ak + 2][am] = ra.z; As[cur ^ 1][ak + 3][am] = ra.w;
            *(float4*)&Bs[cur ^ 1][bk][bn4] = rb;
        }
        __syncthreads();
        cur ^= 1;
    }
    float b0 = 0.f, b1v = 0.f, b2v = 0.f, b3v = 0.f;
    if (bias) {
        const float4 bb = *(const float4*)(bias + bn + tc * 4);
        b0 = bb.x; b1v = bb.y; b2v = bb.z; b3v = bb.w;
    }
#pragma unroll
    for (int i = 0; i < 4; ++i) {
        float2 p0 = up2(acc[i][0]), p1 = up2(acc[i][1]);
        float4 o;
        o.x = p0.x + b0; o.y = p0.y + b1v; o.z = p1.x + b2v; o.w = p1.y + b3v;
        if (dorelu) {
            o.x = fmaxf(o.x, 0.f); o.y = fmaxf(o.y, 0.f);
            o.z = fmaxf(o.z, 0.f); o.w = fmaxf(o.w, 0.f);
        }
        *(float4*)&C[(size_t)(bm + tr * 4 + i) * N + bn + tc * 4] = o;
    }
}

// ---------------- wfeat = g_h @ Ww + bw  (2048 x 32, K=512) ----------------
__global__ void __launch_bounds__(256) wfeat_kernel(const float* __restrict__ Ww,
                                                    const float* __restrict__ bw) {
    int t = blockIdx.x * 256 + threadIdx.x;   // 65536
    int n = t >> 5, oc = t & 31;
    const float* hrow = g_h + (size_t)n * 512;
    float s = bw[oc];
#pragma unroll 8
    for (int k = 0; k < 512; ++k) s += hrow[k] * Ww[k * 32 + oc];
    g_wfeat[t] = s;
}

// ---------------- sequential scan over T=32; state in registers ----------------
__global__ void __launch_bounds__(256) scan_kernel(const float* __restrict__ done,
                                                   const float* __restrict__ state0,
                                                   const int* __restrict__ position,
                                                   float* __restrict__ out_state) {
    const int b = blockIdx.x, j = threadIdx.x;   // j = y*16+x
    float st[32];
#pragma unroll
    for (int c = 0; c < 32; ++c) st[c] = state0[b * 8192 + c * 256 + j];
    for (int t = 0; t < 32; ++t) {
        int idx = t * 64 + b;
        float m = 1.0f - done[idx];
#pragma unroll
        for (int c = 0; c < 32; ++c) st[c] *= m;
        int p0 = position[idx * 2], p1 = position[idx * 2 + 1];
        if (j == p0 * 16 + p1) {
#pragma unroll
            for (int c = 0; c < 32; ++c) st[c] += g_wfeat[idx * 32 + c];
        }
        float* hrow = g_hidden + (size_t)idx * 8256;
#pragma unroll
        for (int c = 0; c < 32; ++c) hrow[c * 256 + j] = st[c];
    }
#pragma unroll
    for (int c = 0; c < 32; ++c) out_state[b * 8192 + c * 256 + j] = st[c];
}

// ---------------- pos_net: one-hot MLP -> hidden cols 8192..8255 ----------------
__global__ void __launch_bounds__(64) posnet_kernel(const int* __restrict__ position,
                                                    const float* __restrict__ wp1,
                                                    const float* __restrict__ bp1,
                                                    const float* __restrict__ wp2,
                                                    const float* __restrict__ bp2) {
    __shared__ float hr[64];
    const int n = blockIdx.x, k = threadIdx.x;
    int p0 = position[n * 2], p1 = position[n * 2 + 1];
    hr[k] = fmaxf(wp1[p0 * 64 + k] + wp1[(16 + p1) * 64 + k] + bp1[k], 0.f);
    __syncthreads();
    float s = bp2[k];
#pragma unroll 8
    for (int j = 0; j < 64; ++j) s += hr[j] * wp2[j * 64 + k];
    g_hidden[(size_t)n * 8256 + 8192 + k] = s;
}

// ---------------- reduce split-K partials + bias + relu ----------------
__global__ void reduce_kernel(const float* __restrict__ bpo1, const float* __restrict__ bv1) {
    int i = blockIdx.x * blockDim.x + threadIdx.x;
    if (i >= 2048 * 128) return;
    float s = 0.f;
#pragma unroll
    for (int ss = 0; ss < 4; ++ss) s += g_part[ss * 262144 + i];
    int nn = i & 127;
    s += (nn < 64) ? bpo1[nn] : bv1[nn - 64];
    g_z[i] = fmaxf(s, 0.f);
}

// ---------------- heads: logits + value ----------------
__global__ void heads_kernel(const float* __restrict__ wpo2, const float* __restrict__ bpo2,
                             const float* __restrict__ wv2, const float* __restrict__ bv2,
                             float* __restrict__ out_logits, float* __restrict__ out_v) {
    int n = blockIdx.x * blockDim.x + threadIdx.x;
    if (n >= 2048) return;
    const float* z = g_z + (size_t)n * 128;
    float lg[5];
#pragma unroll
    for (int a = 0; a < 5; ++a) lg[a] = bpo2[a];
    float vv = bv2[0];
#pragma unroll 4
    for (int j = 0; j < 64; ++j) {
        float zj = z[j];
#pragma unroll
        for (int a = 0; a < 5; ++a) lg[a] += zj * wpo2[j * 5 + a];
        vv += z[64 + j] * wv2[j];
    }
#pragma unroll
    for (int a = 0; a < 5; ++a) out_logits[n * 5 + a] = lg[a];
    out_v[n] = vv;
}

// ---------------- launch ----------------
extern "C" void kernel_launch(void* const* d_in, const int* in_sizes, int n_in,
                              void* d_out, int out_size) {
    bool dict_order = (in_sizes[3] == 4096 && in_sizes[4] == 6144);
    int wb = dict_order ? 4 : 3;
    int posIdx = dict_order ? 3 : 25;

    const float* image  = (const float*)d_in[0];
    const float* done   = (const float*)d_in[1];
    const float* state0 = (const float*)d_in[2];
    const int*   position = (const int*)d_in[posIdx];
    const float* w1  = (const float*)d_in[wb + 0];
    const float* b1  = (const float*)d_in[wb + 1];
    const float* w2  = (const float*)d_in[wb + 2];
    const float* b2  = (const float*)d_in[wb + 3];
    const float* w3  = (const float*)d_in[wb + 4];
    const float* b3  = (const float*)d_in[wb + 5];
    const float* wfc = (const float*)d_in[wb + 6];
    const float* bfc = (const float*)d_in[wb + 7];
    const float* Ww  = (const float*)d_in[wb + 8];
    const float* bw  = (const float*)d_in[wb + 9];
    const float* wp1 = (const float*)d_in[wb + 10];
    const float* bp1 = (const float*)d_in[wb + 11];
    const float* wp2 = (const float*)d_in[wb + 12];
    const float* bp2 = (const float*)d_in[wb + 13];
    const float* wpo1 = (const float*)d_in[wb + 14];
    const float* bpo1 = (const float*)d_in[wb + 15];
    const float* wpo2 = (const float*)d_in[wb + 16];
    const float* bpo2 = (const float*)d_in[wb + 17];
    const float* wv1 = (const float*)d_in[wb + 18];
    const float* bv1 = (const float*)d_in[wb + 19];
    const float* wv2 = (const float*)d_in[wb + 20];
    const float* bv2 = (const float*)d_in[wb + 21];

    float* out = (float*)d_out;
    float* out_logits = out;               // 2048*5
    float* out_v      = out + 10240;       // 2048
    float* out_state  = out + 12288;       // 64*32*16*16

    float *p_a1, *p_a2, *p_a3, *p_h, *p_hidden, *p_w1cat, *p_part;
    float *p_w1t, *p_w2t, *p_w3t;
    cudaGetSymbolAddress((void**)&p_a1, g_a1);
    cudaGetSymbolAddress((void**)&p_a2, g_a2);
    cudaGetSymbolAddress((void**)&p_a3, g_a3);
    cudaGetSymbolAddress((void**)&p_h, g_h);
    cudaGetSymbolAddress((void**)&p_hidden, g_hidden);
    cudaGetSymbolAddress((void**)&p_w1cat, g_w1cat);
    cudaGetSymbolAddress((void**)&p_part, g_part);
    cudaGetSymbolAddress((void**)&p_w1t, g_w1t);
    cudaGetSymbolAddress((void**)&p_w2t, g_w2t);
    cudaGetSymbolAddress((void**)&p_w3t, g_w3t);

    cudaFuncSetAttribute(conv1_kernel, cudaFuncAttributeMaxDynamicSharedMemorySize, 68928);
    cudaFuncSetAttribute(conv2_kernel, cudaFuncAttributeMaxDynamicSharedMemorySize, 57600);
    cudaFuncSetAttribute(conv3_kernel, cudaFuncAttributeMaxDynamicSharedMemorySize, 44064);

    prep_kernel<<<2064, 512>>>(w1, w2, w3, wpo1, wv1);
    conv1_kernel<<<4096, 256, 68928>>>(image, p_w1t, b1, p_a1);
    conv2_kernel<<<2048, 256, 57600>>>(p_a1, p_w2t, b2, p_a2);
    conv3_kernel<<<1024, 256, 44064>>>(p_a2, p_w3t, b3, p_a3);
    // h = relu(a3 @ wfc + bfc): M=2048 N=512 K=3136
    gemm_kernel<<<dim3(8, 32, 1), 256>>>(p_a3, 3136, wfc, 512, p_h,
                                         2048, 512, 3136, 196, bfc, 1);
    wfeat_kernel<<<256, 256>>>(Ww, bw);
    scan_kernel<<<64, 256>>>(done, state0, position, out_state);
    posnet_kernel<<<2048, 64>>>(position, wp1, bp1, wp2, bp2);
    // Z_partials = hidden @ [wpo1|wv1]: M=2048 N=128 K=8256, split-K=4 (129 steps each)
    gemm_kernel<<<dim3(2, 32, 4), 256>>>(p_hidden, 8256, p_w1cat, 128, p_part,
                                         2048, 128, 8256, 129, (const float*)0, 0);
    reduce_kernel<<<512, 512>>>(bpo1, bv1);
    heads_kernel<<<16, 128>>>(wpo2, bpo2, wv2, bv2, out_logits, out_v);
}

// round 4
// speedup vs baseline: 2.2776x; 1.3220x over previous
#include <cuda_runtime.h>

// ---------------- scratch (device globals; no allocation allowed) ----------------
__device__ float g_a1[2048 * 400 * 32];     // conv1 out [n][p=y*20+x][c]
__device__ float g_a2[2048 * 81 * 64];      // conv2 out [n][p][c]
__device__ float g_a3[2048 * 49 * 64];      // conv3 out [n][p*64+c]
__device__ float g_h[2048 * 512];           // CNN feature
__device__ float g_wfeat[2048 * 32];        // h @ Ww + bw
__device__ float g_hidden[2048 * 8256];     // [map readout 8192 | pos_feat 64]
__device__ float g_w1cat[8256 * 128];       // [wpo1 | wv1]
__device__ float g_part[9 * 2048 * 128];    // split-K partials
__device__ float g_z[2048 * 128];           // relu(hidden@W1 + b1)
__device__ float g_w1t[6144];               // conv1 weights [c*64+kykx][oc]
__device__ float g_w2t[32768];              // conv2 weights [ks*32+c][oc]
__device__ float g_w3t[36864];              // conv3 weights [ks*64+c][oc]
__device__ float g_wfcr[3136 * 512];        // wfc re-permuted: [(p*64+c)][nn]

// ---------------- packed f32x2 helpers (B300 FFMA2 path) ----------------
__device__ __forceinline__ unsigned long long pk2(float x) {
    unsigned long long r;
    unsigned u = __float_as_uint(x);
    asm("mov.b64 %0, {%1, %1};" : "=l"(r) : "r"(u));
    return r;
}
__device__ __forceinline__ void fma2(unsigned long long& d, unsigned long long a,
                                     unsigned long long b) {
    asm("fma.rn.f32x2 %0, %1, %2, %0;" : "+l"(d) : "l"(a), "l"(b));
}
__device__ __forceinline__ float2 up2(unsigned long long v) {
    unsigned lo, hi;
    asm("mov.b64 {%0, %1}, %2;" : "=r"(lo), "=r"(hi) : "l"(v));
    return make_float2(__uint_as_float(lo), __uint_as_float(hi));
}

// ---------------- prep: weight transposes / permutes ----------------
__global__ void prep_kernel(const float* __restrict__ w1, const float* __restrict__ w2,
                            const float* __restrict__ w3, const float* __restrict__ wpo1,
                            const float* __restrict__ wv1, const float* __restrict__ wfc) {
    int i = blockIdx.x * blockDim.x + threadIdx.x;
    if (i < 6144) {  // w1 [oc][c][8][8] -> [c*64+kykx][oc]
        int oc = i / 192, r = i - oc * 192;
        g_w1t[r * 32 + oc] = w1[i];
    }
    if (i < 32768) { // w2 [oc][c][4][4] -> [ks*32+c][oc]
        int oc = i >> 9, c = (i >> 4) & 31, kk = i & 15;
        g_w2t[(kk * 32 + c) * 64 + oc] = w2[i];
    }
    if (i < 36864) { // w3 [oc][c][3][3] -> [ks*64+c][oc]
        int oc = i / 576, r = i - oc * 576, c = r / 9, kk = r - c * 9;
        g_w3t[(kk * 64 + c) * 64 + oc] = w3[i];
    }
    if (i < 8256 * 128) {
        int k = i >> 7, nn = i & 127;
        g_w1cat[i] = (nn < 64) ? wpo1[k * 64 + nn] : wv1[k * 64 + nn - 64];
    }
    if (i < 3136 * 512) { // wfc [c*49+p][nn] -> [(p*64+c)][nn]
        int kd = i >> 9, nn = i & 511;
        int p = kd >> 6, c = kd & 63;
        g_wfcr[i] = wfc[(c * 49 + p) * 512 + nn];
    }
}

// ---------------- conv1: 84x84x3 -> 20x20x32, k=8 s=4, half image per block ----------------
__global__ void __launch_bounds__(256) conv1_kernel(const float* __restrict__ img,
                                                    const float* __restrict__ w1t,
                                                    const float* __restrict__ b1,
                                                    float* __restrict__ out) {
    extern __shared__ float sm[];
    float* s_img = sm;            // 44 rows * 252 = 11088
    float* s_w   = sm + 11088;    // 6144
    const int n = blockIdx.x >> 1, h = blockIdx.x & 1;
    const int tid = threadIdx.x;
    const float4* ip = (const float4*)(img + (size_t)n * 21168 + h * (40 * 252));
    for (int i = tid; i < 2772; i += 256) {
        float4 v = ip[i];
        v.x *= (1.f / 255.f); v.y *= (1.f / 255.f);
        v.z *= (1.f / 255.f); v.w *= (1.f / 255.f);
        ((float4*)s_img)[i] = v;
    }
    for (int i = tid; i < 1536; i += 256) ((float4*)s_w)[i] = ((const float4*)w1t)[i];
    __syncthreads();
    const int ocb = (tid & 3) * 8;
    const int pbase = (tid >> 2) * 4;     // valid < 200
    if (pbase >= 200) return;
    float4 bias0 = *(const float4*)(b1 + ocb);
    float4 bias1 = *(const float4*)(b1 + ocb + 4);
    int oy = pbase / 20, ox0 = pbase - oy * 20;
    int iy0 = oy * 4, ix0 = ox0 * 4;
    unsigned long long acc[4][4];
#pragma unroll
    for (int i = 0; i < 4; ++i)
#pragma unroll
        for (int j = 0; j < 4; ++j) acc[i][j] = 0ull;
    for (int ky = 0; ky < 8; ++ky) {
#pragma unroll
        for (int kx = 0; kx < 8; ++kx) {
            int ib = ((iy0 + ky) * 84 + ix0 + kx) * 3;
            const float* wp = s_w + (ky * 8 + kx) * 32 + ocb;
#pragma unroll
            for (int c = 0; c < 3; ++c) {
                unsigned long long v0 = pk2(s_img[ib + c]);
                unsigned long long v1 = pk2(s_img[ib + 12 + c]);
                unsigned long long v2 = pk2(s_img[ib + 24 + c]);
                unsigned long long v3 = pk2(s_img[ib + 36 + c]);
                const ulonglong2* wq = (const ulonglong2*)(wp + c * 2048);
                ulonglong2 wa = wq[0], wb = wq[1];
                fma2(acc[0][0], v0, wa.x); fma2(acc[0][1], v0, wa.y);
                fma2(acc[0][2], v0, wb.x); fma2(acc[0][3], v0, wb.y);
                fma2(acc[1][0], v1, wa.x); fma2(acc[1][1], v1, wa.y);
                fma2(acc[1][2], v1, wb.x); fma2(acc[1][3], v1, wb.y);
                fma2(acc[2][0], v2, wa.x); fma2(acc[2][1], v2, wa.y);
                fma2(acc[2][2], v2, wb.x); fma2(acc[2][3], v2, wb.y);
                fma2(acc[3][0], v3, wa.x); fma2(acc[3][1], v3, wa.y);
                fma2(acc[3][2], v3, wb.x); fma2(acc[3][3], v3, wb.y);
            }
        }
    }
#pragma unroll
    for (int i = 0; i < 4; ++i) {
        float2 p0 = up2(acc[i][0]), p1 = up2(acc[i][1]);
        float2 p2 = up2(acc[i][2]), p3 = up2(acc[i][3]);
        float4 o0, o1;
        o0.x = fmaxf(p0.x + bias0.x, 0.f); o0.y = fmaxf(p0.y + bias0.y, 0.f);
        o0.z = fmaxf(p1.x + bias0.z, 0.f); o0.w = fmaxf(p1.y + bias0.w, 0.f);
        o1.x = fmaxf(p2.x + bias1.x, 0.f); o1.y = fmaxf(p2.y + bias1.y, 0.f);
        o1.z = fmaxf(p3.x + bias1.z, 0.f); o1.w = fmaxf(p3.y + bias1.w, 0.f);
        float* op = out + ((size_t)n * 400 + h * 200 + pbase + i) * 32 + ocb;
        *(float4*)op = o0;
        *(float4*)(op + 4) = o1;
    }
}

// ---------------- unified GEMM / implicit-im2col conv ----------------
// C[M,N] = op(A)[M,K] @ B[K,N]; BM=128, BN=64, BK=16, 256 threads, 8x4 tile (FFMA2).
// MODE 0: A direct [M][lda]; MODE 1: conv2 gather from a1; MODE 2: conv3 gather from a2.
// As stored duplicated (v,v) so LDS.128 yields ready f32x2 broadcast operands.
template<int MODE>
__global__ void __launch_bounds__(256) gemm128(const float* __restrict__ A, int lda,
                                               const float* __restrict__ B, int ldb,
                                               float* __restrict__ C,
                                               int N, int K, int ksteps, int Mtotal,
                                               const float* __restrict__ bias,
                                               int dorelu) {
    __shared__ __align__(16) float As[2][16][256];
    __shared__ __align__(16) float Bs[2][16][64];
    const int bm = blockIdx.y * 128, bn = blockIdx.x * 64;
    const int z = blockIdx.z;
    const int kbeg = z * ksteps * 16;
    const int kend = min(K, kbeg + ksteps * 16);
    C += (size_t)z * Mtotal * N;
    const int tid = threadIdx.x;
    // A-load mapping: thread owns row m_w, k-range [kh, kh+8)
    const int m_w = tid & 127;
    const int kh  = (tid >> 7) * 8;
    const int gm = bm + m_w;
    size_t abase = 0; int oy = 0, ox = 0;
    if (MODE == 0) {
        abase = (size_t)gm * lda;
    } else if (MODE == 1) {
        int n = gm / 81, p = gm - n * 81;
        oy = (p / 9) * 2; ox = (p - (p / 9) * 9) * 2;
        abase = (size_t)n * 12800;
    } else {
        int n = gm / 49, p = gm - n * 49;
        oy = p / 7; ox = p - oy * 7;
        abase = (size_t)n * 5184;
    }
    // B-load mapping
    const int brow = tid >> 4, bcol = (tid & 15) * 4;
    // compute mapping
    const int tr = tid >> 4, tc = tid & 15;

    unsigned long long acc[8][2];
#pragma unroll
    for (int i = 0; i < 8; ++i) { acc[i][0] = 0ull; acc[i][1] = 0ull; }

    auto ldA = [&](int k0, float4& x0, float4& x1) {
        int kidx = k0 + kh;
        const float* p;
        if (MODE == 0) {
            p = A + abase + kidx;
        } else if (MODE == 1) {
            int ks = kidx >> 5;                 // spatial 0..15
            int ky = ks >> 2, kx = ks & 3;
            int pix = (oy + ky) * 20 + ox + kx;
            p = A + abase + pix * 32 + (kidx & 31);
        } else {
            int ks = kidx >> 6;                 // spatial 0..8
            int ky = ks / 3, kx = ks - ky * 3;
            int pix = (oy + ky) * 9 + ox + kx;
            p = A + abase + pix * 64 + (kidx & 63);
        }
        x0 = *(const float4*)p;
        x1 = *(const float4*)(p + 4);
    };
    auto stA = [&](int buf, float4 x0, float4 x1) {
        float* d = &As[buf][kh][2 * m_w];
        *(float2*)(d + 0 * 256) = make_float2(x0.x, x0.x);
        *(float2*)(d + 1 * 256) = make_float2(x0.y, x0.y);
        *(float2*)(d + 2 * 256) = make_float2(x0.z, x0.z);
        *(float2*)(d + 3 * 256) = make_float2(x0.w, x0.w);
        *(float2*)(d + 4 * 256) = make_float2(x1.x, x1.x);
        *(float2*)(d + 5 * 256) = make_float2(x1.y, x1.y);
        *(float2*)(d + 6 * 256) = make_float2(x1.z, x1.z);
        *(float2*)(d + 7 * 256) = make_float2(x1.w, x1.w);
    };

    float4 a0, a1, rb;
    ldA(kbeg, a0, a1);
    rb = *(const float4*)(B + (size_t)(kbeg + brow) * ldb + bn + bcol);
    stA(0, a0, a1);
    *(float4*)&Bs[0][brow][bcol] = rb;
    __syncthreads();

    int cur = 0;
    for (int k0 = kbeg; k0 < kend; k0 += 16) {
        bool more = (k0 + 16) < kend;
        if (more) {
            ldA(k0 + 16, a0, a1);
            rb = *(const float4*)(B + (size_t)(k0 + 16 + brow) * ldb + bn + bcol);
        }
#pragma unroll
        for (int kk = 0; kk < 16; ++kk) {
            const ulonglong2* ap = (const ulonglong2*)&As[cur][kk][tr * 16];
            ulonglong2 A0 = ap[0], A1 = ap[1], A2 = ap[2], A3 = ap[3];
            ulonglong2 Bv = *(const ulonglong2*)&Bs[cur][kk][tc * 4];
            fma2(acc[0][0], A0.x, Bv.x); fma2(acc[0][1], A0.x, Bv.y);
            fma2(acc[1][0], A0.y, Bv.x); fma2(acc[1][1], A0.y, Bv.y);
            fma2(acc[2][0], A1.x, Bv.x); fma2(acc[2][1], A1.x, Bv.y);
            fma2(acc[3][0], A1.y, Bv.x); fma2(acc[3][1], A1.y, Bv.y);
            fma2(acc[4][0], A2.x, Bv.x); fma2(acc[4][1], A2.x, Bv.y);
            fma2(acc[5][0], A2.y, Bv.x); fma2(acc[5][1], A2.y, Bv.y);
            fma2(acc[6][0], A3.x, Bv.x); fma2(acc[6][1], A3.x, Bv.y);
            fma2(acc[7][0], A3.y, Bv.x); fma2(acc[7][1], A3.y, Bv.y);
        }
        if (more) {
            stA(cur ^ 1, a0, a1);
            *(float4*)&Bs[cur ^ 1][brow][bcol] = rb;
        }
        __syncthreads();
        cur ^= 1;
    }

    float4 bb = make_float4(0.f, 0.f, 0.f, 0.f);
    if (bias) bb = *(const float4*)(bias + bn + tc * 4);
#pragma unroll
    for (int i = 0; i < 8; ++i) {
        int m = bm + tr * 8 + i;
        float2 p0 = up2(acc[i][0]), p1 = up2(acc[i][1]);
        float4 o;
        o.x = p0.x + bb.x; o.y = p0.y + bb.y; o.z = p1.x + bb.z; o.w = p1.y + bb.w;
        if (dorelu) {
            o.x = fmaxf(o.x, 0.f); o.y = fmaxf(o.y, 0.f);
            o.z = fmaxf(o.z, 0.f); o.w = fmaxf(o.w, 0.f);
        }
        *(float4*)&C[(size_t)m * N + bn + tc * 4] = o;
    }
}

// ---------------- wfeat = g_h @ Ww + bw  (2048 x 32, K=512) ----------------
__global__ void __launch_bounds__(256) wfeat_kernel(const float* __restrict__ Ww,
                                                    const float* __restrict__ bw) {
    int t = blockIdx.x * 256 + threadIdx.x;   // 65536
    int n = t >> 5, oc = t & 31;
    const float* hrow = g_h + (size_t)n * 512;
    float s = bw[oc];
#pragma unroll 8
    for (int k = 0; k < 512; ++k) s += hrow[k] * Ww[k * 32 + oc];
    g_wfeat[t] = s;
}

// ---------------- sequential scan; state in registers; 4-way channel split ----------------
__global__ void __launch_bounds__(256) scan_kernel(const float* __restrict__ done,
                                                   const float* __restrict__ state0,
                                                   const int* __restrict__ position,
                                                   float* __restrict__ out_state) {
    const int b = blockIdx.x, cq = blockIdx.y * 8, j = threadIdx.x;
    float st[8];
#pragma unroll
    for (int c = 0; c < 8; ++c) st[c] = state0[b * 8192 + (cq + c) * 256 + j];
    for (int t = 0; t < 32; ++t) {
        int idx = t * 64 + b;
        float m = 1.0f - done[idx];
#pragma unroll
        for (int c = 0; c < 8; ++c) st[c] *= m;
        int p0 = position[idx * 2], p1 = position[idx * 2 + 1];
        if (j == p0 * 16 + p1) {
#pragma unroll
            for (int c = 0; c < 8; ++c) st[c] += g_wfeat[idx * 32 + cq + c];
        }
        float* hrow = g_hidden + (size_t)idx * 8256;
#pragma unroll
        for (int c = 0; c < 8; ++c) hrow[(cq + c) * 256 + j] = st[c];
    }
#pragma unroll
    for (int c = 0; c < 8; ++c) out_state[b * 8192 + (cq + c) * 256 + j] = st[c];
}

// ---------------- pos_net: one-hot MLP -> hidden cols 8192..8255 ----------------
__global__ void __launch_bounds__(64) posnet_kernel(const int* __restrict__ position,
                                                    const float* __restrict__ wp1,
                                                    const float* __restrict__ bp1,
                                                    const float* __restrict__ wp2,
                                                    const float* __restrict__ bp2) {
    __shared__ float hr[64];
    const int n = blockIdx.x, k = threadIdx.x;
    int p0 = position[n * 2], p1 = position[n * 2 + 1];
    hr[k] = fmaxf(wp1[p0 * 64 + k] + wp1[(16 + p1) * 64 + k] + bp1[k], 0.f);
    __syncthreads();
    float s = bp2[k];
#pragma unroll 8
    for (int j = 0; j < 64; ++j) s += hr[j] * wp2[j * 64 + k];
    g_hidden[(size_t)n * 8256 + 8192 + k] = s;
}

// ---------------- reduce split-K partials + concat bias + relu ----------------
__global__ void reduce_kernel(const float* __restrict__ bpo1, const float* __restrict__ bv1) {
    int i = blockIdx.x * blockDim.x + threadIdx.x;
    if (i >= 2048 * 128) return;
    float s = 0.f;
#pragma unroll
    for (int ss = 0; ss < 9; ++ss) s += g_part[ss * 262144 + i];
    int nn = i & 127;
    s += (nn < 64) ? bpo1[nn] : bv1[nn - 64];
    g_z[i] = fmaxf(s, 0.f);
}

// ---------------- heads: logits + value ----------------
__global__ void heads_kernel(const float* __restrict__ wpo2, const float* __restrict__ bpo2,
                             const float* __restrict__ wv2, const float* __restrict__ bv2,
                             float* __restrict__ out_logits, float* __restrict__ out_v) {
    int n = blockIdx.x * blockDim.x + threadIdx.x;
    if (n >= 2048) return;
    const float* z = g_z + (size_t)n * 128;
    float lg[5];
#pragma unroll
    for (int a = 0; a < 5; ++a) lg[a] = bpo2[a];
    float vv = bv2[0];
#pragma unroll 4
    for (int j = 0; j < 64; ++j) {
        float zj = z[j];
#pragma unroll
        for (int a = 0; a < 5; ++a) lg[a] += zj * wpo2[j * 5 + a];
        vv += z[64 + j] * wv2[j];
    }
#pragma unroll
    for (int a = 0; a < 5; ++a) out_logits[n * 5 + a] = lg[a];
    out_v[n] = vv;
}

// ---------------- launch ----------------
extern "C" void kernel_launch(void* const* d_in, const int* in_sizes, int n_in,
                              void* d_out, int out_size) {
    bool dict_order = (in_sizes[3] == 4096 && in_sizes[4] == 6144);
    int wb = dict_order ? 4 : 3;
    int posIdx = dict_order ? 3 : 25;

    const float* image  = (const float*)d_in[0];
    const float* done   = (const float*)d_in[1];
    const float* state0 = (const float*)d_in[2];
    const int*   position = (const int*)d_in[posIdx];
    const float* w1  = (const float*)d_in[wb + 0];
    const float* b1  = (const float*)d_in[wb + 1];
    const float* w2  = (const float*)d_in[wb + 2];
    const float* b2  = (const float*)d_in[wb + 3];
    const float* w3  = (const float*)d_in[wb + 4];
    const float* b3  = (const float*)d_in[wb + 5];
    const float* wfc = (const float*)d_in[wb + 6];
    const float* bfc = (const float*)d_in[wb + 7];
    const float* Ww  = (const float*)d_in[wb + 8];
    const float* bw  = (const float*)d_in[wb + 9];
    const float* wp1 = (const float*)d_in[wb + 10];
    const float* bp1 = (const float*)d_in[wb + 11];
    const float* wp2 = (const float*)d_in[wb + 12];
    const float* bp2 = (const float*)d_in[wb + 13];
    const float* wpo1 = (const float*)d_in[wb + 14];
    const float* bpo1 = (const float*)d_in[wb + 15];
    const float* wpo2 = (const float*)d_in[wb + 16];
    const float* bpo2 = (const float*)d_in[wb + 17];
    const float* wv1 = (const float*)d_in[wb + 18];
    const float* bv1 = (const float*)d_in[wb + 19];
    const float* wv2 = (const float*)d_in[wb + 20];
    const float* bv2 = (const float*)d_in[wb + 21];

    float* out = (float*)d_out;
    float* out_logits = out;               // 2048*5
    float* out_v      = out + 10240;       // 2048
    float* out_state  = out + 12288;       // 64*32*16*16

    float *p_a1, *p_a2, *p_a3, *p_h, *p_hidden, *p_w1cat, *p_part;
    float *p_w1t, *p_w2t, *p_w3t, *p_wfcr;
    cudaGetSymbolAddress((void**)&p_a1, g_a1);
    cudaGetSymbolAddress((void**)&p_a2, g_a2);
    cudaGetSymbolAddress((void**)&p_a3, g_a3);
    cudaGetSymbolAddress((void**)&p_h, g_h);
    cudaGetSymbolAddress((void**)&p_hidden, g_hidden);
    cudaGetSymbolAddress((void**)&p_w1cat, g_w1cat);
    cudaGetSymbolAddress((void**)&p_part, g_part);
    cudaGetSymbolAddress((void**)&p_w1t, g_w1t);
    cudaGetSymbolAddress((void**)&p_w2t, g_w2t);
    cudaGetSymbolAddress((void**)&p_w3t, g_w3t);
    cudaGetSymbolAddress((void**)&p_wfcr, g_wfcr);

    cudaFuncSetAttribute(conv1_kernel, cudaFuncAttributeMaxDynamicSharedMemorySize, 68928);

    prep_kernel<<<3137, 512>>>(w1, w2, w3, wpo1, wv1, wfc);
    conv1_kernel<<<4096, 256, 68928>>>(image, p_w1t, b1, p_a1);
    // conv2 as implicit-im2col GEMM: M=2048*81=165888, N=64, K=512
    gemm128<1><<<dim3(1, 1296, 1), 256>>>(p_a1, 0, p_w2t, 64, p_a2,
                                          64, 512, 32, 165888, b2, 1);
    // conv3: M=2048*49=100352, N=64, K=576
    gemm128<2><<<dim3(1, 784, 1), 256>>>(p_a2, 0, p_w3t, 64, p_a3,
                                         64, 576, 36, 100352, b3, 1);
    // FC: M=2048, N=512, K=3136
    gemm128<0><<<dim3(8, 16, 1), 256>>>(p_a3, 3136, p_wfcr, 512, p_h,
                                        512, 3136, 196, 2048, bfc, 1);
    wfeat_kernel<<<256, 256>>>(Ww, bw);
    scan_kernel<<<dim3(64, 4, 1), 256>>>(done, state0, position, out_state);
    posnet_kernel<<<2048, 64>>>(position, wp1, bp1, wp2, bp2);
    // policy/value: M=2048, N=128, K=8256, split-K=9
    gemm128<0><<<dim3(2, 16, 9), 256>>>(p_hidden, 8256, p_w1cat, 128, p_part,
                                        128, 8256, 58, 2048, (const float*)0, 0);
    reduce_kernel<<<512, 512>>>(bpo1, bv1);
    heads_kernel<<<16, 128>>>(wpo2, bpo2, wv2, bv2, out_logits, out_v);
}